// round 12
// baseline (speedup 1.0000x reference)
#include <cuda_runtime.h>
#include <cuda_fp16.h>
#include <math.h>
#include <stdint.h>

// Problem dims (fixed)
#define Bdim 2
#define Mdim 2048
#define Ndim 2048
#define Edim 128
#define Kdim 8
#define Ddim 16
#define NHEAD (Bdim * Kdim)
#define SPLIT 4
#define MCHUNK (Mdim / SPLIT)   // 512 keys per split
#define SHIFT 10.0f             // uniform log2-domain logit shift (softmax-invariant)

// Static scratch (fragment-packed; uint4 = one warp-lane's fragment piece).
__device__ uint4 g_Qh[NHEAD * (size_t)(Ndim / 16) * 32];
__device__ uint4 g_Ql[NHEAD * (size_t)(Ndim / 16) * 32];
__device__ uint4 g_Kh[NHEAD * (size_t)(Mdim / 16) * 32];
__device__ uint4 g_Kl[NHEAD * (size_t)(Mdim / 16) * 32];
__device__ uint4 g_Vh[NHEAD * (size_t)(Mdim / 16) * 32];
__device__ uint4 g_WF[3 * 8 * 8 * 2 * 32];
__device__ uint4 g_W [8 * 16 * 32];
__device__ float g_O [Bdim * (size_t)Ndim * Kdim * Ddim];
__device__ float g_Po[NHEAD * (size_t)SPLIT * Ndim * Ddim];
__device__ float g_Pl[NHEAD * (size_t)SPLIT * Ndim];

__device__ __forceinline__ float ex2f(float x) {
    float r; asm("ex2.approx.f32 %0, %1;" : "=f"(r) : "f"(x)); return r;
}
__device__ __forceinline__ uint32_t pack_h2(float a, float b) {
    __half2 h = __floats2half2_rn(a, b);
    return *reinterpret_cast<uint32_t*>(&h);
}
__device__ __forceinline__ float2 unpack_h2(uint32_t u) {
    __half2 h = *reinterpret_cast<__half2*>(&u);
    return __half22float2(h);
}
__device__ __forceinline__ uint32_t split_lo(float a, float b, uint32_t hi) {
    float2 hf = unpack_h2(hi);
    return pack_h2(a - hf.x, b - hf.y);
}
__device__ __forceinline__ uint32_t movm_t(uint32_t s) {
    uint32_t d;
    asm("movmatrix.sync.aligned.m8n8.trans.b16 %0, %1;" : "=r"(d) : "r"(s));
    return d;
}
__device__ __forceinline__ void cp_async16(uint32_t saddr, const void* g) {
    asm volatile("cp.async.cg.shared.global [%0], [%1], 16;" :: "r"(saddr), "l"(g));
}
#define CP_COMMIT() asm volatile("cp.async.commit_group;" ::: "memory")
#define CP_WAIT1()  asm volatile("cp.async.wait_group 1;" ::: "memory")

__device__ __forceinline__ void mma_f16(float& d0, float& d1, float& d2, float& d3,
                                        uint32_t a0, uint32_t a1, uint32_t a2, uint32_t a3,
                                        uint32_t b0, uint32_t b1) {
    asm volatile("mma.sync.aligned.m16n8k16.row.col.f32.f16.f16.f32 "
                 "{%0,%1,%2,%3},{%4,%5,%6,%7},{%8,%9},{%0,%1,%2,%3};"
                 : "+f"(d0), "+f"(d1), "+f"(d2), "+f"(d3)
                 : "r"(a0), "r"(a1), "r"(a2), "r"(a3), "r"(b0), "r"(b1));
}
__device__ __forceinline__ void mma_f16_c(float& d0, float& d1, float& d2, float& d3,
                                          uint32_t a0, uint32_t a1, uint32_t a2, uint32_t a3,
                                          uint32_t b0, uint32_t b1, float c) {
    asm volatile("mma.sync.aligned.m16n8k16.row.col.f32.f16.f16.f32 "
                 "{%0,%1,%2,%3},{%4,%5,%6,%7},{%8,%9},{%10,%10,%10,%10};"
                 : "=f"(d0), "=f"(d1), "=f"(d2), "=f"(d3)
                 : "r"(a0), "r"(a1), "r"(a2), "r"(a3), "r"(b0), "r"(b1), "f"(c));
}

// ---------------------------------------------------------------------------
// Kernel 0a: pack theta2 into fp16 hi/lo B-fragments (output GEMM).
// ---------------------------------------------------------------------------
__global__ __launch_bounds__(128) void prep_w(const float* __restrict__ t2)
{
    const int idx  = blockIdx.x * 128 + threadIdx.x;
    const int kc   = idx >> 9;
    const int et   = (idx >> 5) & 15;
    const int lane = idx & 31;
    const int g = lane >> 2, t = lane & 3;
    const int e = et * 8 + g;

    const float2 wA = *reinterpret_cast<const float2*>(t2 + ((size_t)kc * Edim + e) * Ddim + 2 * t);
    const float2 wB = *reinterpret_cast<const float2*>(t2 + ((size_t)kc * Edim + e) * Ddim + 2 * t + 8);
    const uint32_t h0 = pack_h2(wA.x, wA.y), l0 = split_lo(wA.x, wA.y, h0);
    const uint32_t h1 = pack_h2(wB.x, wB.y), l1 = split_lo(wB.x, wB.y, h1);
    g_W[(kc * 16 + et) * 32 + lane] = make_uint4(h0, h1, l0, l1);
}

// ---------------------------------------------------------------------------
// Kernel 0b: pack proj weights (l1, t1, l2*sc) into hi/lo B-fragments.
// ---------------------------------------------------------------------------
__global__ __launch_bounds__(128) void prep_proj_w(
    const float* __restrict__ l1, const float* __restrict__ t1, const float* __restrict__ l2)
{
    const int idx  = blockIdx.x * 128 + threadIdx.x;
    const int lane = idx & 31;
    const int nt   = (idx >> 5) & 1;
    const int c    = (idx >> 6) & 7;
    const int k    = (idx >> 9) & 7;
    const int a    = idx >> 12;
    const int g = lane >> 2, t = lane & 3;

    const float* W = (a == 0) ? l1 : (a == 1) ? t1 : l2;
    const float s  = (a == 2) ? (0.25f * 1.4426950408889634f) : 1.0f;
    const int d  = nt * 8 + g;
    const int e0 = c * 16 + 2 * t;

    const float w00 = W[((size_t)k * Edim + e0    ) * Ddim + d] * s;
    const float w01 = W[((size_t)k * Edim + e0 + 1) * Ddim + d] * s;
    const float w10 = W[((size_t)k * Edim + e0 + 8) * Ddim + d] * s;
    const float w11 = W[((size_t)k * Edim + e0 + 9) * Ddim + d] * s;
    const uint32_t h0 = pack_h2(w00, w01), lo0 = split_lo(w00, w01, h0);
    const uint32_t h1 = pack_h2(w10, w11), lo1 = split_lo(w10, w11, h1);
    g_WF[((a * 8 + k) * 8 + c) * 64 + nt * 32 + lane] = make_uint4(h0, h1, lo0, lo1);
}

// ---------------------------------------------------------------------------
// Kernel 1: projections as fp16 hi/lo MMA (3-pass Dekker), register-exact
// packing into the flash fragment layouts (K/Q: pair-pack; V: movmatrix).
// ---------------------------------------------------------------------------
__global__ __launch_bounds__(128) void proj_mma(
    const float* __restrict__ x, const float* __restrict__ y,
    const float* __restrict__ bl)
{
    const int warp = threadIdx.x >> 5;
    const int lane = threadIdx.x & 31;
    const int g = lane >> 2, t = lane & 3;
    const int tile = blockIdx.x * 4 + warp;
    const int hp   = blockIdx.y;
    const bool isQ = (blockIdx.z != 0);
    const int row0 = tile * 16;
    const int b    = row0 >> 11;
    const int m0   = row0 & (Mdim - 1);

    const float* src = isQ ? y : x;
    uint32_t ahi[8][4], alo[8][4];
    #pragma unroll
    for (int c = 0; c < 8; c++) {
        const float* base = src + (size_t)row0 * Edim + c * 16;
        const float2 v0 = *reinterpret_cast<const float2*>(base + (g    ) * Edim + 2 * t);
        const float2 v1 = *reinterpret_cast<const float2*>(base + (g + 8) * Edim + 2 * t);
        const float2 v2 = *reinterpret_cast<const float2*>(base + (g    ) * Edim + 2 * t + 8);
        const float2 v3 = *reinterpret_cast<const float2*>(base + (g + 8) * Edim + 2 * t + 8);
        ahi[c][0] = pack_h2(v0.x, v0.y); alo[c][0] = split_lo(v0.x, v0.y, ahi[c][0]);
        ahi[c][1] = pack_h2(v1.x, v1.y); alo[c][1] = split_lo(v1.x, v1.y, ahi[c][1]);
        ahi[c][2] = pack_h2(v2.x, v2.y); alo[c][2] = split_lo(v2.x, v2.y, ahi[c][2]);
        ahi[c][3] = pack_h2(v3.x, v3.y); alo[c][3] = split_lo(v3.x, v3.y, ahi[c][3]);
    }

    #pragma unroll
    for (int hh = 0; hh < 2; hh++) {
        const int k = hp * 2 + hh;
        const int head = b * Kdim + k;
        const size_t oidx = ((size_t)head * (Mdim / 16) + (m0 >> 4)) * 32 + lane;

        if (!isQ) {
            float cK[2][4], cV[2][4];
            #pragma unroll
            for (int nt = 0; nt < 2; nt++)
                #pragma unroll
                for (int i = 0; i < 4; i++) { cK[nt][i] = 0.f; cV[nt][i] = 0.f; }

            #pragma unroll
            for (int c = 0; c < 8; c++) {
                #pragma unroll
                for (int nt = 0; nt < 2; nt++) {
                    const uint4 wK = g_WF[((0 * 8 + k) * 8 + c) * 64 + nt * 32 + lane];
                    mma_f16(cK[nt][0], cK[nt][1], cK[nt][2], cK[nt][3],
                            ahi[c][0], ahi[c][1], ahi[c][2], ahi[c][3], wK.x, wK.y);
                    mma_f16(cK[nt][0], cK[nt][1], cK[nt][2], cK[nt][3],
                            alo[c][0], alo[c][1], alo[c][2], alo[c][3], wK.x, wK.y);
                    mma_f16(cK[nt][0], cK[nt][1], cK[nt][2], cK[nt][3],
                            ahi[c][0], ahi[c][1], ahi[c][2], ahi[c][3], wK.z, wK.w);
                    const uint4 wV = g_WF[((1 * 8 + k) * 8 + c) * 64 + nt * 32 + lane];
                    mma_f16(cV[nt][0], cV[nt][1], cV[nt][2], cV[nt][3],
                            ahi[c][0], ahi[c][1], ahi[c][2], ahi[c][3], wV.x, wV.y);
                    mma_f16(cV[nt][0], cV[nt][1], cV[nt][2], cV[nt][3],
                            alo[c][0], alo[c][1], alo[c][2], alo[c][3], wV.x, wV.y);
                    mma_f16(cV[nt][0], cV[nt][1], cV[nt][2], cV[nt][3],
                            ahi[c][0], ahi[c][1], ahi[c][2], ahi[c][3], wV.z, wV.w);
                }
            }

            const float2 bl0 = *reinterpret_cast<const float2*>(bl + k * Ddim + 2 * t);
            const float2 bl1 = *reinterpret_cast<const float2*>(bl + k * Ddim + 8 + 2 * t);
            cK[0][0] += bl0.x; cK[0][1] += bl0.y; cK[0][2] += bl0.x; cK[0][3] += bl0.y;
            cK[1][0] += bl1.x; cK[1][1] += bl1.y; cK[1][2] += bl1.x; cK[1][3] += bl1.y;

            uint4 kh, kl;
            kh.x = pack_h2(cK[0][0], cK[0][1]); kl.x = split_lo(cK[0][0], cK[0][1], kh.x);
            kh.y = pack_h2(cK[1][0], cK[1][1]); kl.y = split_lo(cK[1][0], cK[1][1], kh.y);
            kh.z = pack_h2(cK[0][2], cK[0][3]); kl.z = split_lo(cK[0][2], cK[0][3], kh.z);
            kh.w = pack_h2(cK[1][2], cK[1][3]); kl.w = split_lo(cK[1][2], cK[1][3], kh.w);
            g_Kh[oidx] = kh;
            g_Kl[oidx] = kl;

            uint4 vv;
            vv.x = movm_t(pack_h2(cV[0][0], cV[0][1]));
            vv.y = movm_t(pack_h2(cV[0][2], cV[0][3]));
            vv.z = movm_t(pack_h2(cV[1][0], cV[1][1]));
            vv.w = movm_t(pack_h2(cV[1][2], cV[1][3]));
            g_Vh[oidx] = vv;
        } else {
            float cQ[2][4];
            #pragma unroll
            for (int nt = 0; nt < 2; nt++)
                #pragma unroll
                for (int i = 0; i < 4; i++) cQ[nt][i] = 0.f;

            #pragma unroll
            for (int c = 0; c < 8; c++) {
                #pragma unroll
                for (int nt = 0; nt < 2; nt++) {
                    const uint4 wQ = g_WF[((2 * 8 + k) * 8 + c) * 64 + nt * 32 + lane];
                    mma_f16(cQ[nt][0], cQ[nt][1], cQ[nt][2], cQ[nt][3],
                            ahi[c][0], ahi[c][1], ahi[c][2], ahi[c][3], wQ.x, wQ.y);
                    mma_f16(cQ[nt][0], cQ[nt][1], cQ[nt][2], cQ[nt][3],
                            alo[c][0], alo[c][1], alo[c][2], alo[c][3], wQ.x, wQ.y);
                    mma_f16(cQ[nt][0], cQ[nt][1], cQ[nt][2], cQ[nt][3],
                            ahi[c][0], ahi[c][1], ahi[c][2], ahi[c][3], wQ.z, wQ.w);
                }
            }
            uint4 qh, ql;
            qh.x = pack_h2(cQ[0][0], cQ[0][1]); ql.x = split_lo(cQ[0][0], cQ[0][1], qh.x);
            qh.y = pack_h2(cQ[0][2], cQ[0][3]); ql.y = split_lo(cQ[0][2], cQ[0][3], qh.y);
            qh.z = pack_h2(cQ[1][0], cQ[1][1]); ql.z = split_lo(cQ[1][0], cQ[1][1], qh.z);
            qh.w = pack_h2(cQ[1][2], cQ[1][3]); ql.w = split_lo(cQ[1][2], cQ[1][3], qh.w);
            g_Qh[oidx] = qh;
            g_Ql[oidx] = ql;
        }
    }
}

// ---------------------------------------------------------------------------
// Kernel 2: flash attention, fp16 hi/lo mma, split-K, cp.async smem pipeline.
// 64 queries/warp (4 A-fragments) amortize K/V smem reads + loop overhead.
// lsum on the fma pipe via HADD2 trees (tensor pipe relieved of ones-MMA).
// ---------------------------------------------------------------------------
__global__ __launch_bounds__(128, 4) void flash_kernel()
{
    __shared__ __align__(16) uint4 sbuf[3][96];   // [stage][arr*32 + lane]

    const int head = blockIdx.y;
    const int sp   = blockIdx.z;
    const int tid  = threadIdx.x;
    const int warp = tid >> 5;
    const int lane = tid & 31;
    const int g = lane >> 2, t = lane & 3;
    const int qb = blockIdx.x * 256 + warp * 64;   // 64 queries per warp

    uint4 qh[4], ql[4];
    #pragma unroll
    for (int f = 0; f < 4; f++) {
        const size_t qidx = ((size_t)head * (Ndim / 16) + (qb >> 4) + f) * 32 + lane;
        qh[f] = g_Qh[qidx];
        ql[f] = g_Ql[qidx];
    }

    float o[4][8];
    float lsum[4][2];
    #pragma unroll
    for (int f = 0; f < 4; f++) {
        #pragma unroll
        for (int i = 0; i < 8; i++) o[f][i] = 0.f;
        lsum[f][0] = 0.f; lsum[f][1] = 0.f;
    }

    const int kb0 = sp * (MCHUNK / 16);
    const int nkb = MCHUNK / 16;                       // 32

    const size_t hb = (size_t)head * (Mdim / 16) * 32;
    const uint4* gsrc =
        (warp == 0) ? (g_Kh + hb + lane) :
        (warp == 1) ? (g_Kl + hb + lane) :
                      (g_Vh + hb + lane);
    const bool producer = (tid < 96);

    if (producer)
        cp_async16((uint32_t)__cvta_generic_to_shared(&sbuf[0][warp * 32 + lane]),
                   gsrc + (size_t)kb0 * 32);
    CP_COMMIT();
    if (producer)
        cp_async16((uint32_t)__cvta_generic_to_shared(&sbuf[1][warp * 32 + lane]),
                   gsrc + (size_t)(kb0 + 1) * 32);
    CP_COMMIT();

    #pragma unroll 2
    for (int i = 0; i < nkb; i++) {
        CP_WAIT1();
        __syncthreads();

        const int st = i % 3;
        const uint4 kh = sbuf[st][lane];
        const uint4 kl = sbuf[st][32 + lane];
        const uint4 vv = sbuf[st][64 + lane];

        #pragma unroll
        for (int f = 0; f < 4; f++) {
            float s0, s1, s2, s3;
            mma_f16_c(s0, s1, s2, s3, qh[f].x, qh[f].y, qh[f].z, qh[f].w, kh.x, kh.y, -SHIFT);
            mma_f16  (s0, s1, s2, s3, ql[f].x, ql[f].y, ql[f].z, ql[f].w, kh.x, kh.y);
            mma_f16  (s0, s1, s2, s3, qh[f].x, qh[f].y, qh[f].z, qh[f].w, kl.x, kl.y);
            float u0, u1, u2, u3;
            mma_f16_c(u0, u1, u2, u3, qh[f].x, qh[f].y, qh[f].z, qh[f].w, kh.z, kh.w, -SHIFT);
            mma_f16  (u0, u1, u2, u3, ql[f].x, ql[f].y, ql[f].z, ql[f].w, kh.z, kh.w);
            mma_f16  (u0, u1, u2, u3, qh[f].x, qh[f].y, qh[f].z, qh[f].w, kl.z, kl.w);

            const __half2 p0 = __floats2half2_rn(ex2f(s0), ex2f(s1));  // row g,   keys 0-7
            const __half2 p1 = __floats2half2_rn(ex2f(s2), ex2f(s3));  // row g+8, keys 0-7
            const __half2 p2 = __floats2half2_rn(ex2f(u0), ex2f(u1));  // row g,   keys 8-15
            const __half2 p3 = __floats2half2_rn(ex2f(u2), ex2f(u3));  // row g+8, keys 8-15

            // lsum on the fma pipe: per-thread partial over this thread's 4 cols/row
            const __half2 se = __hadd2(p0, p2);
            const __half2 so = __hadd2(p1, p3);
            lsum[f][0] += __low2float(se) + __high2float(se);
            lsum[f][1] += __low2float(so) + __high2float(so);

            const uint32_t a0 = *reinterpret_cast<const uint32_t*>(&p0);
            const uint32_t a1 = *reinterpret_cast<const uint32_t*>(&p1);
            const uint32_t a2 = *reinterpret_cast<const uint32_t*>(&p2);
            const uint32_t a3 = *reinterpret_cast<const uint32_t*>(&p3);

            mma_f16(o[f][0], o[f][1], o[f][2], o[f][3], a0, a1, a2, a3, vv.x, vv.y);
            mma_f16(o[f][4], o[f][5], o[f][6], o[f][7], a0, a1, a2, a3, vv.z, vv.w);
        }

        if (i + 2 < nkb && producer)
            cp_async16((uint32_t)__cvta_generic_to_shared(&sbuf[(i + 2) % 3][warp * 32 + lane]),
                       gsrc + (size_t)(kb0 + i + 2) * 32);
        CP_COMMIT();
    }

    const size_t pb = ((size_t)head * SPLIT + sp) * Ndim;
    #pragma unroll
    for (int f = 0; f < 4; f++) {
        float l0 = lsum[f][0], l1 = lsum[f][1];
        l0 += __shfl_xor_sync(0xffffffffu, l0, 1);
        l0 += __shfl_xor_sync(0xffffffffu, l0, 2);
        l1 += __shfl_xor_sync(0xffffffffu, l1, 1);
        l1 += __shfl_xor_sync(0xffffffffu, l1, 2);
        const int rlo = qb + 16*f + g;
        const int rhi = rlo + 8;
        if (t == 0) {
            g_Pl[pb + rlo] = l0;
            g_Pl[pb + rhi] = l1;
        }
        #pragma unroll
        for (int c = 0; c < 2; c++) {
            const int d0 = 8 * c + 2 * t;
            *reinterpret_cast<float2*>(g_Po + (pb + rlo) * Ddim + d0) =
                make_float2(o[f][4*c+0], o[f][4*c+1]);
            *reinterpret_cast<float2*>(g_Po + (pb + rhi) * Ddim + d0) =
                make_float2(o[f][4*c+2], o[f][4*c+3]);
        }
    }
}

// ---------------------------------------------------------------------------
// Kernel 2b: combine — one thread per (head, n, d-quad), fully coalesced.
// ---------------------------------------------------------------------------
__global__ __launch_bounds__(128) void combine_kernel(const float* __restrict__ bt)
{
    const int idx  = blockIdx.x * 128 + threadIdx.x;
    const int head = idx >> 13;
    const int n    = (idx >> 2) & (Ndim - 1);
    const int quad = idx & 3;

    float L = 0.f;
    float4 o = make_float4(0.f, 0.f, 0.f, 0.f);
    #pragma unroll
    for (int s = 0; s < SPLIT; s++) {
        const size_t pb = ((size_t)head * SPLIT + s) * Ndim + n;
        L += g_Pl[pb];
        const float4 v = reinterpret_cast<const float4*>(g_Po)[pb * 4 + quad];
        o.x += v.x; o.y += v.y; o.z += v.z; o.w += v.w;
    }
    const float inv = 1.f / L;

    const int b = head >> 3, k = head & 7;
    const float4 bb = reinterpret_cast<const float4*>(bt)[k * 4 + quad];
    float4 r;
    r.x = o.x * inv + bb.x;
    r.y = o.y * inv + bb.y;
    r.z = o.z * inv + bb.z;
    r.w = o.w * inv + bb.w;
    reinterpret_cast<float4*>(g_O)[(((size_t)(b * Ndim + n)) * Kdim + k) * 4 + quad] = r;
}

// ---------------------------------------------------------------------------
// Kernel 3: output projection as fp16 hi/lo tensor-core GEMM.
// ---------------------------------------------------------------------------
__global__ __launch_bounds__(128) void out_kernel(float* __restrict__ out)
{
    const int row0 = blockIdx.x * 16;
    const int warp = threadIdx.x >> 5;
    const int lane = threadIdx.x & 31;
    const int g = lane >> 2, t = lane & 3;

    float acc[4][4];
    #pragma unroll
    for (int e4 = 0; e4 < 4; e4++)
        #pragma unroll
        for (int i = 0; i < 4; i++) acc[e4][i] = 0.f;

    const float* Orl = g_O + (size_t)(row0 + g    ) * 128;
    const float* Orh = g_O + (size_t)(row0 + g + 8) * 128;

    #pragma unroll
    for (int kc = 0; kc < 8; kc++) {
        const float2 xA = *reinterpret_cast<const float2*>(Orl + kc * 16 + 2 * t);
        const float2 yA = *reinterpret_cast<const float2*>(Orh + kc * 16 + 2 * t);
        const float2 xB = *reinterpret_cast<const float2*>(Orl + kc * 16 + 2 * t + 8);
        const float2 yB = *reinterpret_cast<const float2*>(Orh + kc * 16 + 2 * t + 8);
        const uint32_t ah0 = pack_h2(xA.x, xA.y), al0 = split_lo(xA.x, xA.y, ah0);
        const uint32_t ah1 = pack_h2(yA.x, yA.y), al1 = split_lo(yA.x, yA.y, ah1);
        const uint32_t ah2 = pack_h2(xB.x, xB.y), al2 = split_lo(xB.x, xB.y, ah2);
        const uint32_t ah3 = pack_h2(yB.x, yB.y), al3 = split_lo(yB.x, yB.y, ah3);

        #pragma unroll
        for (int e4 = 0; e4 < 4; e4++) {
            const uint4 wv = g_W[(kc * 16 + (warp * 4 + e4)) * 32 + lane];
            mma_f16(acc[e4][0], acc[e4][1], acc[e4][2], acc[e4][3], ah0, ah1, ah2, ah3, wv.x, wv.y);
            mma_f16(acc[e4][0], acc[e4][1], acc[e4][2], acc[e4][3], al0, al1, al2, al3, wv.x, wv.y);
            mma_f16(acc[e4][0], acc[e4][1], acc[e4][2], acc[e4][3], ah0, ah1, ah2, ah3, wv.z, wv.w);
        }
    }

    #pragma unroll
    for (int e4 = 0; e4 < 4; e4++) {
        const int e0 = (warp * 4 + e4) * 8 + 2 * t;
        *reinterpret_cast<float2*>(out + (size_t)(row0 + g    ) * Edim + e0) =
            make_float2(acc[e4][0], acc[e4][1]);
        *reinterpret_cast<float2*>(out + (size_t)(row0 + g + 8) * Edim + e0) =
            make_float2(acc[e4][2], acc[e4][3]);
    }
}

extern "C" void kernel_launch(void* const* d_in, const int* in_sizes, int n_in,
                              void* d_out, int out_size)
{
    const float* x  = (const float*)d_in[0];
    const float* y  = (const float*)d_in[1];
    const float* l1 = (const float*)d_in[2];
    const float* l2 = (const float*)d_in[3];
    const float* t1 = (const float*)d_in[4];
    const float* t2 = (const float*)d_in[5];
    const float* bl = (const float*)d_in[6];
    const float* bt = (const float*)d_in[7];

    prep_w<<<32, 128>>>(t2);
    prep_proj_w<<<96, 128>>>(l1, t1, l2);
    proj_mma<<<dim3(64, 4, 2), 128>>>(x, y, bl);
    flash_kernel<<<dim3(Ndim / 256, NHEAD, SPLIT), 128>>>();
    combine_kernel<<<NHEAD * Ndim * 4 / 128, 128>>>(bt);
    out_kernel<<<Bdim * Ndim / 16, 128>>>((float*)d_out);
}

// round 13
// speedup vs baseline: 1.0429x; 1.0429x over previous
#include <cuda_runtime.h>
#include <cuda_fp16.h>
#include <math.h>
#include <stdint.h>

// Problem dims (fixed)
#define Bdim 2
#define Mdim 2048
#define Ndim 2048
#define Edim 128
#define Kdim 8
#define Ddim 16
#define NHEAD (Bdim * Kdim)
#define SPLIT 4
#define MCHUNK (Mdim / SPLIT)   // 512 keys per split
#define SHIFT 10.0f             // uniform log2-domain logit shift (softmax-invariant)

// Static scratch (fragment-packed; uint4 = one warp-lane's fragment piece).
__device__ uint4 g_Qh[NHEAD * (size_t)(Ndim / 16) * 32];
__device__ uint4 g_Ql[NHEAD * (size_t)(Ndim / 16) * 32];
__device__ uint4 g_Kh[NHEAD * (size_t)(Mdim / 16) * 32];
__device__ uint4 g_Kl[NHEAD * (size_t)(Mdim / 16) * 32];
__device__ uint4 g_Vh[NHEAD * (size_t)(Mdim / 16) * 32];
__device__ uint4 g_WF[3 * 8 * 8 * 2 * 32];
__device__ uint4 g_W [8 * 16 * 32];
__device__ float g_O [Bdim * (size_t)Ndim * Kdim * Ddim];
__device__ float g_Po[NHEAD * (size_t)SPLIT * Ndim * Ddim];
__device__ float g_Pl[NHEAD * (size_t)SPLIT * Ndim];

__device__ __forceinline__ float ex2f(float x) {
    float r; asm("ex2.approx.f32 %0, %1;" : "=f"(r) : "f"(x)); return r;
}
__device__ __forceinline__ uint32_t pack_h2(float a, float b) {
    __half2 h = __floats2half2_rn(a, b);
    return *reinterpret_cast<uint32_t*>(&h);
}
__device__ __forceinline__ float2 unpack_h2(uint32_t u) {
    __half2 h = *reinterpret_cast<__half2*>(&u);
    return __half22float2(h);
}
__device__ __forceinline__ uint32_t split_lo(float a, float b, uint32_t hi) {
    float2 hf = unpack_h2(hi);
    return pack_h2(a - hf.x, b - hf.y);
}
__device__ __forceinline__ uint32_t movm_t(uint32_t s) {
    uint32_t d;
    asm("movmatrix.sync.aligned.m8n8.trans.b16 %0, %1;" : "=r"(d) : "r"(s));
    return d;
}
__device__ __forceinline__ void cp_async16(uint32_t saddr, const void* g) {
    asm volatile("cp.async.cg.shared.global [%0], [%1], 16;" :: "r"(saddr), "l"(g));
}
#define CP_COMMIT() asm volatile("cp.async.commit_group;" ::: "memory")
#define CP_WAIT1()  asm volatile("cp.async.wait_group 1;" ::: "memory")

__device__ __forceinline__ void mma_f16(float& d0, float& d1, float& d2, float& d3,
                                        uint32_t a0, uint32_t a1, uint32_t a2, uint32_t a3,
                                        uint32_t b0, uint32_t b1) {
    asm volatile("mma.sync.aligned.m16n8k16.row.col.f32.f16.f16.f32 "
                 "{%0,%1,%2,%3},{%4,%5,%6,%7},{%8,%9},{%0,%1,%2,%3};"
                 : "+f"(d0), "+f"(d1), "+f"(d2), "+f"(d3)
                 : "r"(a0), "r"(a1), "r"(a2), "r"(a3), "r"(b0), "r"(b1));
}
__device__ __forceinline__ void mma_f16_c(float& d0, float& d1, float& d2, float& d3,
                                          uint32_t a0, uint32_t a1, uint32_t a2, uint32_t a3,
                                          uint32_t b0, uint32_t b1, float c) {
    asm volatile("mma.sync.aligned.m16n8k16.row.col.f32.f16.f16.f32 "
                 "{%0,%1,%2,%3},{%4,%5,%6,%7},{%8,%9},{%10,%10,%10,%10};"
                 : "=f"(d0), "=f"(d1), "=f"(d2), "=f"(d3)
                 : "r"(a0), "r"(a1), "r"(a2), "r"(a3), "r"(b0), "r"(b1), "f"(c));
}

// ---------------------------------------------------------------------------
// Kernel 0a: pack theta2 into fp16 hi/lo B-fragments (output GEMM).
// ---------------------------------------------------------------------------
__global__ __launch_bounds__(128) void prep_w(const float* __restrict__ t2)
{
    const int idx  = blockIdx.x * 128 + threadIdx.x;
    const int kc   = idx >> 9;
    const int et   = (idx >> 5) & 15;
    const int lane = idx & 31;
    const int g = lane >> 2, t = lane & 3;
    const int e = et * 8 + g;

    const float2 wA = *reinterpret_cast<const float2*>(t2 + ((size_t)kc * Edim + e) * Ddim + 2 * t);
    const float2 wB = *reinterpret_cast<const float2*>(t2 + ((size_t)kc * Edim + e) * Ddim + 2 * t + 8);
    const uint32_t h0 = pack_h2(wA.x, wA.y), l0 = split_lo(wA.x, wA.y, h0);
    const uint32_t h1 = pack_h2(wB.x, wB.y), l1 = split_lo(wB.x, wB.y, h1);
    g_W[(kc * 16 + et) * 32 + lane] = make_uint4(h0, h1, l0, l1);
}

// ---------------------------------------------------------------------------
// Kernel 0b: pack proj weights (l1, t1, l2*sc) into hi/lo B-fragments.
// ---------------------------------------------------------------------------
__global__ __launch_bounds__(128) void prep_proj_w(
    const float* __restrict__ l1, const float* __restrict__ t1, const float* __restrict__ l2)
{
    const int idx  = blockIdx.x * 128 + threadIdx.x;
    const int lane = idx & 31;
    const int nt   = (idx >> 5) & 1;
    const int c    = (idx >> 6) & 7;
    const int k    = (idx >> 9) & 7;
    const int a    = idx >> 12;
    const int g = lane >> 2, t = lane & 3;

    const float* W = (a == 0) ? l1 : (a == 1) ? t1 : l2;
    const float s  = (a == 2) ? (0.25f * 1.4426950408889634f) : 1.0f;
    const int d  = nt * 8 + g;
    const int e0 = c * 16 + 2 * t;

    const float w00 = W[((size_t)k * Edim + e0    ) * Ddim + d] * s;
    const float w01 = W[((size_t)k * Edim + e0 + 1) * Ddim + d] * s;
    const float w10 = W[((size_t)k * Edim + e0 + 8) * Ddim + d] * s;
    const float w11 = W[((size_t)k * Edim + e0 + 9) * Ddim + d] * s;
    const uint32_t h0 = pack_h2(w00, w01), lo0 = split_lo(w00, w01, h0);
    const uint32_t h1 = pack_h2(w10, w11), lo1 = split_lo(w10, w11, h1);
    g_WF[((a * 8 + k) * 8 + c) * 64 + nt * 32 + lane] = make_uint4(h0, h1, lo0, lo1);
}

// ---------------------------------------------------------------------------
// Kernel 1: projections as fp16 hi/lo MMA (3-pass Dekker), register-exact
// packing into the flash fragment layouts (K/Q: pair-pack; V: movmatrix).
// ---------------------------------------------------------------------------
__global__ __launch_bounds__(128) void proj_mma(
    const float* __restrict__ x, const float* __restrict__ y,
    const float* __restrict__ bl)
{
    const int warp = threadIdx.x >> 5;
    const int lane = threadIdx.x & 31;
    const int g = lane >> 2, t = lane & 3;
    const int tile = blockIdx.x * 4 + warp;
    const int hp   = blockIdx.y;
    const bool isQ = (blockIdx.z != 0);
    const int row0 = tile * 16;
    const int b    = row0 >> 11;
    const int m0   = row0 & (Mdim - 1);

    const float* src = isQ ? y : x;
    uint32_t ahi[8][4], alo[8][4];
    #pragma unroll
    for (int c = 0; c < 8; c++) {
        const float* base = src + (size_t)row0 * Edim + c * 16;
        const float2 v0 = *reinterpret_cast<const float2*>(base + (g    ) * Edim + 2 * t);
        const float2 v1 = *reinterpret_cast<const float2*>(base + (g + 8) * Edim + 2 * t);
        const float2 v2 = *reinterpret_cast<const float2*>(base + (g    ) * Edim + 2 * t + 8);
        const float2 v3 = *reinterpret_cast<const float2*>(base + (g + 8) * Edim + 2 * t + 8);
        ahi[c][0] = pack_h2(v0.x, v0.y); alo[c][0] = split_lo(v0.x, v0.y, ahi[c][0]);
        ahi[c][1] = pack_h2(v1.x, v1.y); alo[c][1] = split_lo(v1.x, v1.y, ahi[c][1]);
        ahi[c][2] = pack_h2(v2.x, v2.y); alo[c][2] = split_lo(v2.x, v2.y, ahi[c][2]);
        ahi[c][3] = pack_h2(v3.x, v3.y); alo[c][3] = split_lo(v3.x, v3.y, ahi[c][3]);
    }

    #pragma unroll
    for (int hh = 0; hh < 2; hh++) {
        const int k = hp * 2 + hh;
        const int head = b * Kdim + k;
        const size_t oidx = ((size_t)head * (Mdim / 16) + (m0 >> 4)) * 32 + lane;

        if (!isQ) {
            float cK[2][4], cV[2][4];
            #pragma unroll
            for (int nt = 0; nt < 2; nt++)
                #pragma unroll
                for (int i = 0; i < 4; i++) { cK[nt][i] = 0.f; cV[nt][i] = 0.f; }

            #pragma unroll
            for (int c = 0; c < 8; c++) {
                #pragma unroll
                for (int nt = 0; nt < 2; nt++) {
                    const uint4 wK = g_WF[((0 * 8 + k) * 8 + c) * 64 + nt * 32 + lane];
                    mma_f16(cK[nt][0], cK[nt][1], cK[nt][2], cK[nt][3],
                            ahi[c][0], ahi[c][1], ahi[c][2], ahi[c][3], wK.x, wK.y);
                    mma_f16(cK[nt][0], cK[nt][1], cK[nt][2], cK[nt][3],
                            alo[c][0], alo[c][1], alo[c][2], alo[c][3], wK.x, wK.y);
                    mma_f16(cK[nt][0], cK[nt][1], cK[nt][2], cK[nt][3],
                            ahi[c][0], ahi[c][1], ahi[c][2], ahi[c][3], wK.z, wK.w);
                    const uint4 wV = g_WF[((1 * 8 + k) * 8 + c) * 64 + nt * 32 + lane];
                    mma_f16(cV[nt][0], cV[nt][1], cV[nt][2], cV[nt][3],
                            ahi[c][0], ahi[c][1], ahi[c][2], ahi[c][3], wV.x, wV.y);
                    mma_f16(cV[nt][0], cV[nt][1], cV[nt][2], cV[nt][3],
                            alo[c][0], alo[c][1], alo[c][2], alo[c][3], wV.x, wV.y);
                    mma_f16(cV[nt][0], cV[nt][1], cV[nt][2], cV[nt][3],
                            ahi[c][0], ahi[c][1], ahi[c][2], ahi[c][3], wV.z, wV.w);
                }
            }

            const float2 bl0 = *reinterpret_cast<const float2*>(bl + k * Ddim + 2 * t);
            const float2 bl1 = *reinterpret_cast<const float2*>(bl + k * Ddim + 8 + 2 * t);
            cK[0][0] += bl0.x; cK[0][1] += bl0.y; cK[0][2] += bl0.x; cK[0][3] += bl0.y;
            cK[1][0] += bl1.x; cK[1][1] += bl1.y; cK[1][2] += bl1.x; cK[1][3] += bl1.y;

            uint4 kh, kl;
            kh.x = pack_h2(cK[0][0], cK[0][1]); kl.x = split_lo(cK[0][0], cK[0][1], kh.x);
            kh.y = pack_h2(cK[1][0], cK[1][1]); kl.y = split_lo(cK[1][0], cK[1][1], kh.y);
            kh.z = pack_h2(cK[0][2], cK[0][3]); kl.z = split_lo(cK[0][2], cK[0][3], kh.z);
            kh.w = pack_h2(cK[1][2], cK[1][3]); kl.w = split_lo(cK[1][2], cK[1][3], kh.w);
            g_Kh[oidx] = kh;
            g_Kl[oidx] = kl;

            uint4 vv;
            vv.x = movm_t(pack_h2(cV[0][0], cV[0][1]));
            vv.y = movm_t(pack_h2(cV[0][2], cV[0][3]));
            vv.z = movm_t(pack_h2(cV[1][0], cV[1][1]));
            vv.w = movm_t(pack_h2(cV[1][2], cV[1][3]));
            g_Vh[oidx] = vv;
        } else {
            float cQ[2][4];
            #pragma unroll
            for (int nt = 0; nt < 2; nt++)
                #pragma unroll
                for (int i = 0; i < 4; i++) cQ[nt][i] = 0.f;

            #pragma unroll
            for (int c = 0; c < 8; c++) {
                #pragma unroll
                for (int nt = 0; nt < 2; nt++) {
                    const uint4 wQ = g_WF[((2 * 8 + k) * 8 + c) * 64 + nt * 32 + lane];
                    mma_f16(cQ[nt][0], cQ[nt][1], cQ[nt][2], cQ[nt][3],
                            ahi[c][0], ahi[c][1], ahi[c][2], ahi[c][3], wQ.x, wQ.y);
                    mma_f16(cQ[nt][0], cQ[nt][1], cQ[nt][2], cQ[nt][3],
                            alo[c][0], alo[c][1], alo[c][2], alo[c][3], wQ.x, wQ.y);
                    mma_f16(cQ[nt][0], cQ[nt][1], cQ[nt][2], cQ[nt][3],
                            ahi[c][0], ahi[c][1], ahi[c][2], ahi[c][3], wQ.z, wQ.w);
                }
            }
            uint4 qh, ql;
            qh.x = pack_h2(cQ[0][0], cQ[0][1]); ql.x = split_lo(cQ[0][0], cQ[0][1], qh.x);
            qh.y = pack_h2(cQ[0][2], cQ[0][3]); ql.y = split_lo(cQ[0][2], cQ[0][3], qh.y);
            qh.z = pack_h2(cQ[1][0], cQ[1][1]); ql.z = split_lo(cQ[1][0], cQ[1][1], qh.z);
            qh.w = pack_h2(cQ[1][2], cQ[1][3]); ql.w = split_lo(cQ[1][2], cQ[1][3], qh.w);
            g_Qh[oidx] = qh;
            g_Ql[oidx] = ql;
        }
    }
}

// ---------------------------------------------------------------------------
// Kernel 2: flash attention, fp16 hi/lo mma, split-K, cp.async smem pipeline.
// 32 queries/warp (R11 shape — best measured); lsum on the fma pipe via
// HADD2 trees, relieving the tensor pipe of the ones-MMA (9 -> 8 MMAs/tile).
// ---------------------------------------------------------------------------
__global__ __launch_bounds__(128) void flash_kernel()
{
    __shared__ __align__(16) uint4 sbuf[3][96];   // [stage][arr*32 + lane]

    const int head = blockIdx.y;
    const int sp   = blockIdx.z;
    const int tid  = threadIdx.x;
    const int warp = tid >> 5;
    const int lane = tid & 31;
    const int g = lane >> 2, t = lane & 3;
    const int qb = blockIdx.x * 128 + warp * 32;

    uint4 qh[2], ql[2];
    #pragma unroll
    for (int f = 0; f < 2; f++) {
        const size_t qidx = ((size_t)head * (Ndim / 16) + (qb >> 4) + f) * 32 + lane;
        qh[f] = g_Qh[qidx];
        ql[f] = g_Ql[qidx];
    }

    float o[2][8];
    float lsum[2][2];
    #pragma unroll
    for (int f = 0; f < 2; f++) {
        #pragma unroll
        for (int i = 0; i < 8; i++) o[f][i] = 0.f;
        lsum[f][0] = 0.f; lsum[f][1] = 0.f;
    }

    const int kb0 = sp * (MCHUNK / 16);
    const int nkb = MCHUNK / 16;                       // 32

    const size_t hb = (size_t)head * (Mdim / 16) * 32;
    const uint4* gsrc =
        (warp == 0) ? (g_Kh + hb + lane) :
        (warp == 1) ? (g_Kl + hb + lane) :
                      (g_Vh + hb + lane);
    const bool producer = (tid < 96);

    if (producer)
        cp_async16((uint32_t)__cvta_generic_to_shared(&sbuf[0][warp * 32 + lane]),
                   gsrc + (size_t)kb0 * 32);
    CP_COMMIT();
    if (producer)
        cp_async16((uint32_t)__cvta_generic_to_shared(&sbuf[1][warp * 32 + lane]),
                   gsrc + (size_t)(kb0 + 1) * 32);
    CP_COMMIT();

    #pragma unroll 4
    for (int i = 0; i < nkb; i++) {
        CP_WAIT1();
        __syncthreads();

        const int st = i % 3;
        const uint4 kh = sbuf[st][lane];
        const uint4 kl = sbuf[st][32 + lane];
        const uint4 vv = sbuf[st][64 + lane];

        #pragma unroll
        for (int f = 0; f < 2; f++) {
            float s0, s1, s2, s3;
            mma_f16_c(s0, s1, s2, s3, qh[f].x, qh[f].y, qh[f].z, qh[f].w, kh.x, kh.y, -SHIFT);
            mma_f16  (s0, s1, s2, s3, ql[f].x, ql[f].y, ql[f].z, ql[f].w, kh.x, kh.y);
            mma_f16  (s0, s1, s2, s3, qh[f].x, qh[f].y, qh[f].z, qh[f].w, kl.x, kl.y);
            float u0, u1, u2, u3;
            mma_f16_c(u0, u1, u2, u3, qh[f].x, qh[f].y, qh[f].z, qh[f].w, kh.z, kh.w, -SHIFT);
            mma_f16  (u0, u1, u2, u3, ql[f].x, ql[f].y, ql[f].z, ql[f].w, kh.z, kh.w);
            mma_f16  (u0, u1, u2, u3, qh[f].x, qh[f].y, qh[f].z, qh[f].w, kl.z, kl.w);

            const __half2 p0 = __floats2half2_rn(ex2f(s0), ex2f(s1));  // row g,   keys 0-7
            const __half2 p1 = __floats2half2_rn(ex2f(s2), ex2f(s3));  // row g+8, keys 0-7
            const __half2 p2 = __floats2half2_rn(ex2f(u0), ex2f(u1));  // row g,   keys 8-15
            const __half2 p3 = __floats2half2_rn(ex2f(u2), ex2f(u3));  // row g+8, keys 8-15

            // lsum on the fma pipe (exact same fp16-rounded weights as PV)
            const __half2 se = __hadd2(p0, p2);
            const __half2 so = __hadd2(p1, p3);
            lsum[f][0] += __low2float(se) + __high2float(se);
            lsum[f][1] += __low2float(so) + __high2float(so);

            const uint32_t a0 = *reinterpret_cast<const uint32_t*>(&p0);
            const uint32_t a1 = *reinterpret_cast<const uint32_t*>(&p1);
            const uint32_t a2 = *reinterpret_cast<const uint32_t*>(&p2);
            const uint32_t a3 = *reinterpret_cast<const uint32_t*>(&p3);

            mma_f16(o[f][0], o[f][1], o[f][2], o[f][3], a0, a1, a2, a3, vv.x, vv.y);
            mma_f16(o[f][4], o[f][5], o[f][6], o[f][7], a0, a1, a2, a3, vv.z, vv.w);
        }

        if (i + 2 < nkb && producer)
            cp_async16((uint32_t)__cvta_generic_to_shared(&sbuf[(i + 2) % 3][warp * 32 + lane]),
                       gsrc + (size_t)(kb0 + i + 2) * 32);
        CP_COMMIT();
    }

    const size_t pb = ((size_t)head * SPLIT + sp) * Ndim;
    #pragma unroll
    for (int f = 0; f < 2; f++) {
        float l0 = lsum[f][0], l1 = lsum[f][1];
        l0 += __shfl_xor_sync(0xffffffffu, l0, 1);
        l0 += __shfl_xor_sync(0xffffffffu, l0, 2);
        l1 += __shfl_xor_sync(0xffffffffu, l1, 1);
        l1 += __shfl_xor_sync(0xffffffffu, l1, 2);
        const int rlo = qb + 16*f + g;
        const int rhi = rlo + 8;
        if (t == 0) {
            g_Pl[pb + rlo] = l0;
            g_Pl[pb + rhi] = l1;
        }
        #pragma unroll
        for (int c = 0; c < 2; c++) {
            const int d0 = 8 * c + 2 * t;
            *reinterpret_cast<float2*>(g_Po + (pb + rlo) * Ddim + d0) =
                make_float2(o[f][4*c+0], o[f][4*c+1]);
            *reinterpret_cast<float2*>(g_Po + (pb + rhi) * Ddim + d0) =
                make_float2(o[f][4*c+2], o[f][4*c+3]);
        }
    }
}

// ---------------------------------------------------------------------------
// Kernel 2b: combine — one thread per (head, n, d-quad), fully coalesced.
// ---------------------------------------------------------------------------
__global__ __launch_bounds__(128) void combine_kernel(const float* __restrict__ bt)
{
    const int idx  = blockIdx.x * 128 + threadIdx.x;
    const int head = idx >> 13;
    const int n    = (idx >> 2) & (Ndim - 1);
    const int quad = idx & 3;

    float L = 0.f;
    float4 o = make_float4(0.f, 0.f, 0.f, 0.f);
    #pragma unroll
    for (int s = 0; s < SPLIT; s++) {
        const size_t pb = ((size_t)head * SPLIT + s) * Ndim + n;
        L += g_Pl[pb];
        const float4 v = reinterpret_cast<const float4*>(g_Po)[pb * 4 + quad];
        o.x += v.x; o.y += v.y; o.z += v.z; o.w += v.w;
    }
    const float inv = 1.f / L;

    const int b = head >> 3, k = head & 7;
    const float4 bb = reinterpret_cast<const float4*>(bt)[k * 4 + quad];
    float4 r;
    r.x = o.x * inv + bb.x;
    r.y = o.y * inv + bb.y;
    r.z = o.z * inv + bb.z;
    r.w = o.w * inv + bb.w;
    reinterpret_cast<float4*>(g_O)[(((size_t)(b * Ndim + n)) * Kdim + k) * 4 + quad] = r;
}

// ---------------------------------------------------------------------------
// Kernel 3: output projection as fp16 hi/lo tensor-core GEMM.
// ---------------------------------------------------------------------------
__global__ __launch_bounds__(128) void out_kernel(float* __restrict__ out)
{
    const int row0 = blockIdx.x * 16;
    const int warp = threadIdx.x >> 5;
    const int lane = threadIdx.x & 31;
    const int g = lane >> 2, t = lane & 3;

    float acc[4][4];
    #pragma unroll
    for (int e4 = 0; e4 < 4; e4++)
        #pragma unroll
        for (int i = 0; i < 4; i++) acc[e4][i] = 0.f;

    const float* Orl = g_O + (size_t)(row0 + g    ) * 128;
    const float* Orh = g_O + (size_t)(row0 + g + 8) * 128;

    #pragma unroll
    for (int kc = 0; kc < 8; kc++) {
        const float2 xA = *reinterpret_cast<const float2*>(Orl + kc * 16 + 2 * t);
        const float2 yA = *reinterpret_cast<const float2*>(Orh + kc * 16 + 2 * t);
        const float2 xB = *reinterpret_cast<const float2*>(Orl + kc * 16 + 2 * t + 8);
        const float2 yB = *reinterpret_cast<const float2*>(Orh + kc * 16 + 2 * t + 8);
        const uint32_t ah0 = pack_h2(xA.x, xA.y), al0 = split_lo(xA.x, xA.y, ah0);
        const uint32_t ah1 = pack_h2(yA.x, yA.y), al1 = split_lo(yA.x, yA.y, ah1);
        const uint32_t ah2 = pack_h2(xB.x, xB.y), al2 = split_lo(xB.x, xB.y, ah2);
        const uint32_t ah3 = pack_h2(yB.x, yB.y), al3 = split_lo(yB.x, yB.y, ah3);

        #pragma unroll
        for (int e4 = 0; e4 < 4; e4++) {
            const uint4 wv = g_W[(kc * 16 + (warp * 4 + e4)) * 32 + lane];
            mma_f16(acc[e4][0], acc[e4][1], acc[e4][2], acc[e4][3], ah0, ah1, ah2, ah3, wv.x, wv.y);
            mma_f16(acc[e4][0], acc[e4][1], acc[e4][2], acc[e4][3], al0, al1, al2, al3, wv.x, wv.y);
            mma_f16(acc[e4][0], acc[e4][1], acc[e4][2], acc[e4][3], ah0, ah1, ah2, ah3, wv.z, wv.w);
        }
    }

    #pragma unroll
    for (int e4 = 0; e4 < 4; e4++) {
        const int e0 = (warp * 4 + e4) * 8 + 2 * t;
        *reinterpret_cast<float2*>(out + (size_t)(row0 + g    ) * Edim + e0) =
            make_float2(acc[e4][0], acc[e4][1]);
        *reinterpret_cast<float2*>(out + (size_t)(row0 + g + 8) * Edim + e0) =
            make_float2(acc[e4][2], acc[e4][3]);
    }
}

extern "C" void kernel_launch(void* const* d_in, const int* in_sizes, int n_in,
                              void* d_out, int out_size)
{
    const float* x  = (const float*)d_in[0];
    const float* y  = (const float*)d_in[1];
    const float* l1 = (const float*)d_in[2];
    const float* l2 = (const float*)d_in[3];
    const float* t1 = (const float*)d_in[4];
    const float* t2 = (const float*)d_in[5];
    const float* bl = (const float*)d_in[6];
    const float* bt = (const float*)d_in[7];

    prep_w<<<32, 128>>>(t2);
    prep_proj_w<<<96, 128>>>(l1, t1, l2);
    proj_mma<<<dim3(64, 4, 2), 128>>>(x, y, bl);
    flash_kernel<<<dim3(Ndim / 128, NHEAD, SPLIT), 128>>>();
    combine_kernel<<<NHEAD * Ndim * 4 / 128, 128>>>(bt);
    out_kernel<<<Bdim * Ndim / 16, 128>>>((float*)d_out);
}

// round 14
// speedup vs baseline: 1.1635x; 1.1156x over previous
#include <cuda_runtime.h>
#include <cuda_fp16.h>
#include <math.h>
#include <stdint.h>

// Problem dims (fixed)
#define Bdim 2
#define Mdim 2048
#define Ndim 2048
#define Edim 128
#define Kdim 8
#define Ddim 16
#define NHEAD (Bdim * Kdim)
#define SPLIT 4
#define MCHUNK (Mdim / SPLIT)   // 512 keys per split
#define SHIFT 10.0f             // uniform log2-domain logit shift (softmax-invariant)

// Static scratch (fragment-packed; uint4 = one warp-lane's fragment piece).
__device__ uint4 g_Qh[NHEAD * (size_t)(Ndim / 16) * 32];
__device__ uint4 g_Ql[NHEAD * (size_t)(Ndim / 16) * 32];
__device__ uint4 g_Kh[NHEAD * (size_t)(Mdim / 16) * 32];
__device__ uint4 g_Kl[NHEAD * (size_t)(Mdim / 16) * 32];
__device__ uint4 g_Vh[NHEAD * (size_t)(Mdim / 16) * 32];
__device__ uint4 g_WF[3 * 8 * 8 * 2 * 32];
__device__ uint4 g_W [8 * 16 * 32];
__device__ float g_O [Bdim * (size_t)Ndim * Kdim * Ddim];
__device__ float g_Po[NHEAD * (size_t)SPLIT * Ndim * Ddim];
__device__ float g_Pl[NHEAD * (size_t)SPLIT * Ndim];

__device__ __forceinline__ float ex2f(float x) {
    float r; asm("ex2.approx.f32 %0, %1;" : "=f"(r) : "f"(x)); return r;
}
__device__ __forceinline__ uint32_t pack_h2(float a, float b) {
    __half2 h = __floats2half2_rn(a, b);
    return *reinterpret_cast<uint32_t*>(&h);
}
__device__ __forceinline__ float2 unpack_h2(uint32_t u) {
    __half2 h = *reinterpret_cast<__half2*>(&u);
    return __half22float2(h);
}
__device__ __forceinline__ uint32_t split_lo(float a, float b, uint32_t hi) {
    float2 hf = unpack_h2(hi);
    return pack_h2(a - hf.x, b - hf.y);
}
__device__ __forceinline__ uint32_t movm_t(uint32_t s) {
    uint32_t d;
    asm("movmatrix.sync.aligned.m8n8.trans.b16 %0, %1;" : "=r"(d) : "r"(s));
    return d;
}
__device__ __forceinline__ void cp_async16(uint32_t saddr, const void* g) {
    asm volatile("cp.async.cg.shared.global [%0], [%1], 16;" :: "r"(saddr), "l"(g));
}
#define CP_COMMIT() asm volatile("cp.async.commit_group;" ::: "memory")
#define CP_WAIT1()  asm volatile("cp.async.wait_group 1;" ::: "memory")

__device__ __forceinline__ void mma_f16(float& d0, float& d1, float& d2, float& d3,
                                        uint32_t a0, uint32_t a1, uint32_t a2, uint32_t a3,
                                        uint32_t b0, uint32_t b1) {
    asm volatile("mma.sync.aligned.m16n8k16.row.col.f32.f16.f16.f32 "
                 "{%0,%1,%2,%3},{%4,%5,%6,%7},{%8,%9},{%0,%1,%2,%3};"
                 : "+f"(d0), "+f"(d1), "+f"(d2), "+f"(d3)
                 : "r"(a0), "r"(a1), "r"(a2), "r"(a3), "r"(b0), "r"(b1));
}
__device__ __forceinline__ void mma_f16_c(float& d0, float& d1, float& d2, float& d3,
                                          uint32_t a0, uint32_t a1, uint32_t a2, uint32_t a3,
                                          uint32_t b0, uint32_t b1, float c) {
    asm volatile("mma.sync.aligned.m16n8k16.row.col.f32.f16.f16.f32 "
                 "{%0,%1,%2,%3},{%4,%5,%6,%7},{%8,%9},{%10,%10,%10,%10};"
                 : "=f"(d0), "=f"(d1), "=f"(d2), "=f"(d3)
                 : "r"(a0), "r"(a1), "r"(a2), "r"(a3), "r"(b0), "r"(b1), "f"(c));
}

// ---------------------------------------------------------------------------
// Kernel 0: merged weight prep. Blocks [0,32): theta2 -> g_W.
// Blocks [32,128): proj weights (l1, t1, l2*sc) -> g_WF.
// ---------------------------------------------------------------------------
__global__ __launch_bounds__(128) void prep_all(
    const float* __restrict__ t2,
    const float* __restrict__ l1, const float* __restrict__ t1,
    const float* __restrict__ l2)
{
    if (blockIdx.x < 32) {
        const int idx  = blockIdx.x * 128 + threadIdx.x;   // 0..4095
        const int kc   = idx >> 9;
        const int et   = (idx >> 5) & 15;
        const int lane = idx & 31;
        const int g = lane >> 2, t = lane & 3;
        const int e = et * 8 + g;

        const float2 wA = *reinterpret_cast<const float2*>(t2 + ((size_t)kc * Edim + e) * Ddim + 2 * t);
        const float2 wB = *reinterpret_cast<const float2*>(t2 + ((size_t)kc * Edim + e) * Ddim + 2 * t + 8);
        const uint32_t h0 = pack_h2(wA.x, wA.y), l0 = split_lo(wA.x, wA.y, h0);
        const uint32_t h1 = pack_h2(wB.x, wB.y), l1v = split_lo(wB.x, wB.y, h1);
        g_W[(kc * 16 + et) * 32 + lane] = make_uint4(h0, h1, l0, l1v);
    } else {
        const int idx  = (blockIdx.x - 32) * 128 + threadIdx.x;  // 0..12287
        const int lane = idx & 31;
        const int nt   = (idx >> 5) & 1;
        const int c    = (idx >> 6) & 7;
        const int k    = (idx >> 9) & 7;
        const int a    = idx >> 12;
        const int g = lane >> 2, t = lane & 3;

        const float* W = (a == 0) ? l1 : (a == 1) ? t1 : l2;
        const float s  = (a == 2) ? (0.25f * 1.4426950408889634f) : 1.0f;
        const int d  = nt * 8 + g;
        const int e0 = c * 16 + 2 * t;

        const float w00 = W[((size_t)k * Edim + e0    ) * Ddim + d] * s;
        const float w01 = W[((size_t)k * Edim + e0 + 1) * Ddim + d] * s;
        const float w10 = W[((size_t)k * Edim + e0 + 8) * Ddim + d] * s;
        const float w11 = W[((size_t)k * Edim + e0 + 9) * Ddim + d] * s;
        const uint32_t h0 = pack_h2(w00, w01), lo0 = split_lo(w00, w01, h0);
        const uint32_t h1 = pack_h2(w10, w11), lo1 = split_lo(w10, w11, h1);
        g_WF[((a * 8 + k) * 8 + c) * 64 + nt * 32 + lane] = make_uint4(h0, h1, lo0, lo1);
    }
}

// ---------------------------------------------------------------------------
// Kernel 1: projections as fp16 hi/lo MMA (3-pass Dekker), register-exact
// packing into the flash fragment layouts (K/Q: pair-pack; V: movmatrix).
// ---------------------------------------------------------------------------
__global__ __launch_bounds__(128) void proj_mma(
    const float* __restrict__ x, const float* __restrict__ y,
    const float* __restrict__ bl)
{
    const int warp = threadIdx.x >> 5;
    const int lane = threadIdx.x & 31;
    const int g = lane >> 2, t = lane & 3;
    const int tile = blockIdx.x * 4 + warp;
    const int hp   = blockIdx.y;
    const bool isQ = (blockIdx.z != 0);
    const int row0 = tile * 16;
    const int b    = row0 >> 11;
    const int m0   = row0 & (Mdim - 1);

    const float* src = isQ ? y : x;
    uint32_t ahi[8][4], alo[8][4];
    #pragma unroll
    for (int c = 0; c < 8; c++) {
        const float* base = src + (size_t)row0 * Edim + c * 16;
        const float2 v0 = *reinterpret_cast<const float2*>(base + (g    ) * Edim + 2 * t);
        const float2 v1 = *reinterpret_cast<const float2*>(base + (g + 8) * Edim + 2 * t);
        const float2 v2 = *reinterpret_cast<const float2*>(base + (g    ) * Edim + 2 * t + 8);
        const float2 v3 = *reinterpret_cast<const float2*>(base + (g + 8) * Edim + 2 * t + 8);
        ahi[c][0] = pack_h2(v0.x, v0.y); alo[c][0] = split_lo(v0.x, v0.y, ahi[c][0]);
        ahi[c][1] = pack_h2(v1.x, v1.y); alo[c][1] = split_lo(v1.x, v1.y, ahi[c][1]);
        ahi[c][2] = pack_h2(v2.x, v2.y); alo[c][2] = split_lo(v2.x, v2.y, ahi[c][2]);
        ahi[c][3] = pack_h2(v3.x, v3.y); alo[c][3] = split_lo(v3.x, v3.y, ahi[c][3]);
    }

    #pragma unroll
    for (int hh = 0; hh < 2; hh++) {
        const int k = hp * 2 + hh;
        const int head = b * Kdim + k;
        const size_t oidx = ((size_t)head * (Mdim / 16) + (m0 >> 4)) * 32 + lane;

        if (!isQ) {
            float cK[2][4], cV[2][4];
            #pragma unroll
            for (int nt = 0; nt < 2; nt++)
                #pragma unroll
                for (int i = 0; i < 4; i++) { cK[nt][i] = 0.f; cV[nt][i] = 0.f; }

            #pragma unroll
            for (int c = 0; c < 8; c++) {
                #pragma unroll
                for (int nt = 0; nt < 2; nt++) {
                    const uint4 wK = g_WF[((0 * 8 + k) * 8 + c) * 64 + nt * 32 + lane];
                    mma_f16(cK[nt][0], cK[nt][1], cK[nt][2], cK[nt][3],
                            ahi[c][0], ahi[c][1], ahi[c][2], ahi[c][3], wK.x, wK.y);
                    mma_f16(cK[nt][0], cK[nt][1], cK[nt][2], cK[nt][3],
                            alo[c][0], alo[c][1], alo[c][2], alo[c][3], wK.x, wK.y);
                    mma_f16(cK[nt][0], cK[nt][1], cK[nt][2], cK[nt][3],
                            ahi[c][0], ahi[c][1], ahi[c][2], ahi[c][3], wK.z, wK.w);
                    const uint4 wV = g_WF[((1 * 8 + k) * 8 + c) * 64 + nt * 32 + lane];
                    mma_f16(cV[nt][0], cV[nt][1], cV[nt][2], cV[nt][3],
                            ahi[c][0], ahi[c][1], ahi[c][2], ahi[c][3], wV.x, wV.y);
                    mma_f16(cV[nt][0], cV[nt][1], cV[nt][2], cV[nt][3],
                            alo[c][0], alo[c][1], alo[c][2], alo[c][3], wV.x, wV.y);
                    mma_f16(cV[nt][0], cV[nt][1], cV[nt][2], cV[nt][3],
                            ahi[c][0], ahi[c][1], ahi[c][2], ahi[c][3], wV.z, wV.w);
                }
            }

            const float2 bl0 = *reinterpret_cast<const float2*>(bl + k * Ddim + 2 * t);
            const float2 bl1 = *reinterpret_cast<const float2*>(bl + k * Ddim + 8 + 2 * t);
            cK[0][0] += bl0.x; cK[0][1] += bl0.y; cK[0][2] += bl0.x; cK[0][3] += bl0.y;
            cK[1][0] += bl1.x; cK[1][1] += bl1.y; cK[1][2] += bl1.x; cK[1][3] += bl1.y;

            uint4 kh, kl;
            kh.x = pack_h2(cK[0][0], cK[0][1]); kl.x = split_lo(cK[0][0], cK[0][1], kh.x);
            kh.y = pack_h2(cK[1][0], cK[1][1]); kl.y = split_lo(cK[1][0], cK[1][1], kh.y);
            kh.z = pack_h2(cK[0][2], cK[0][3]); kl.z = split_lo(cK[0][2], cK[0][3], kh.z);
            kh.w = pack_h2(cK[1][2], cK[1][3]); kl.w = split_lo(cK[1][2], cK[1][3], kh.w);
            g_Kh[oidx] = kh;
            g_Kl[oidx] = kl;

            uint4 vv;
            vv.x = movm_t(pack_h2(cV[0][0], cV[0][1]));
            vv.y = movm_t(pack_h2(cV[0][2], cV[0][3]));
            vv.z = movm_t(pack_h2(cV[1][0], cV[1][1]));
            vv.w = movm_t(pack_h2(cV[1][2], cV[1][3]));
            g_Vh[oidx] = vv;
        } else {
            float cQ[2][4];
            #pragma unroll
            for (int nt = 0; nt < 2; nt++)
                #pragma unroll
                for (int i = 0; i < 4; i++) cQ[nt][i] = 0.f;

            #pragma unroll
            for (int c = 0; c < 8; c++) {
                #pragma unroll
                for (int nt = 0; nt < 2; nt++) {
                    const uint4 wQ = g_WF[((2 * 8 + k) * 8 + c) * 64 + nt * 32 + lane];
                    mma_f16(cQ[nt][0], cQ[nt][1], cQ[nt][2], cQ[nt][3],
                            ahi[c][0], ahi[c][1], ahi[c][2], ahi[c][3], wQ.x, wQ.y);
                    mma_f16(cQ[nt][0], cQ[nt][1], cQ[nt][2], cQ[nt][3],
                            alo[c][0], alo[c][1], alo[c][2], alo[c][3], wQ.x, wQ.y);
                    mma_f16(cQ[nt][0], cQ[nt][1], cQ[nt][2], cQ[nt][3],
                            ahi[c][0], ahi[c][1], ahi[c][2], ahi[c][3], wQ.z, wQ.w);
                }
            }
            uint4 qh, ql;
            qh.x = pack_h2(cQ[0][0], cQ[0][1]); ql.x = split_lo(cQ[0][0], cQ[0][1], qh.x);
            qh.y = pack_h2(cQ[0][2], cQ[0][3]); ql.y = split_lo(cQ[0][2], cQ[0][3], qh.y);
            qh.z = pack_h2(cQ[1][0], cQ[1][1]); ql.z = split_lo(cQ[1][0], cQ[1][1], qh.z);
            qh.w = pack_h2(cQ[1][2], cQ[1][3]); ql.w = split_lo(cQ[1][2], cQ[1][3], qh.w);
            g_Qh[oidx] = qh;
            g_Ql[oidx] = ql;
        }
    }
}

// ---------------------------------------------------------------------------
// Kernel 2: flash attention, fp16 hi/lo mma, split-K, cp.async smem pipeline.
// R11 math (ones-MMA lsum — the issue-minimal form) with TWO key-tiles per
// pipeline stage: half the barriers, commits, and loop arithmetic.
// ---------------------------------------------------------------------------
__global__ __launch_bounds__(128) void flash_kernel()
{
    __shared__ __align__(16) uint4 sbuf[3][192];  // [stage][tile*96 + arr*32 + lane]

    const int head = blockIdx.y;
    const int sp   = blockIdx.z;
    const int tid  = threadIdx.x;
    const int warp = tid >> 5;
    const int lane = tid & 31;
    const int g = lane >> 2, t = lane & 3;
    const int qb = blockIdx.x * 128 + warp * 32;

    uint4 qh[2], ql[2];
    #pragma unroll
    for (int f = 0; f < 2; f++) {
        const size_t qidx = ((size_t)head * (Ndim / 16) + (qb >> 4) + f) * 32 + lane;
        qh[f] = g_Qh[qidx];
        ql[f] = g_Ql[qidx];
    }

    // ones-in-column-0 B fragment: lanes 0-3 hold {1,1}h2 in b0 and b1
    const uint32_t ones = (g == 0) ? 0x3C003C00u : 0u;

    float o[2][8];
    float lac[2][4];
    #pragma unroll
    for (int f = 0; f < 2; f++) {
        #pragma unroll
        for (int i = 0; i < 8; i++) o[f][i] = 0.f;
        #pragma unroll
        for (int i = 0; i < 4; i++) lac[f][i] = 0.f;
    }

    const int kb0   = sp * (MCHUNK / 16);
    const int nstep = MCHUNK / 32;                 // 16 double-tile steps

    const size_t hb = (size_t)head * (Mdim / 16) * 32;
    const uint4* gsrc =
        (warp == 0) ? (g_Kh + hb + lane) :
        (warp == 1) ? (g_Kl + hb + lane) :
                      (g_Vh + hb + lane);
    const bool producer = (tid < 96);
    const uint32_t sdst = (uint32_t)__cvta_generic_to_shared(&sbuf[0][warp * 32 + lane]);

    // prologue: stages 0 and 1 (tiles 0..3)
    if (producer) {
        cp_async16(sdst,                     gsrc + (size_t)(kb0    ) * 32);
        cp_async16(sdst + 96 * 16,           gsrc + (size_t)(kb0 + 1) * 32);
    }
    CP_COMMIT();
    if (producer) {
        cp_async16(sdst + 192 * 16,          gsrc + (size_t)(kb0 + 2) * 32);
        cp_async16(sdst + (192 + 96) * 16,   gsrc + (size_t)(kb0 + 3) * 32);
    }
    CP_COMMIT();

    #pragma unroll 2
    for (int i = 0; i < nstep; i++) {
        CP_WAIT1();
        __syncthreads();

        const int st = i % 3;
        #pragma unroll
        for (int j = 0; j < 2; j++) {
            const uint4 kh = sbuf[st][j * 96 + lane];
            const uint4 kl = sbuf[st][j * 96 + 32 + lane];
            const uint4 vv = sbuf[st][j * 96 + 64 + lane];

            #pragma unroll
            for (int f = 0; f < 2; f++) {
                float s0, s1, s2, s3;
                mma_f16_c(s0, s1, s2, s3, qh[f].x, qh[f].y, qh[f].z, qh[f].w, kh.x, kh.y, -SHIFT);
                mma_f16  (s0, s1, s2, s3, ql[f].x, ql[f].y, ql[f].z, ql[f].w, kh.x, kh.y);
                mma_f16  (s0, s1, s2, s3, qh[f].x, qh[f].y, qh[f].z, qh[f].w, kl.x, kl.y);
                float u0, u1, u2, u3;
                mma_f16_c(u0, u1, u2, u3, qh[f].x, qh[f].y, qh[f].z, qh[f].w, kh.z, kh.w, -SHIFT);
                mma_f16  (u0, u1, u2, u3, ql[f].x, ql[f].y, ql[f].z, ql[f].w, kh.z, kh.w);
                mma_f16  (u0, u1, u2, u3, qh[f].x, qh[f].y, qh[f].z, qh[f].w, kl.z, kl.w);

                const uint32_t a0 = pack_h2(ex2f(s0), ex2f(s1));
                const uint32_t a1 = pack_h2(ex2f(s2), ex2f(s3));
                const uint32_t a2 = pack_h2(ex2f(u0), ex2f(u1));
                const uint32_t a3 = pack_h2(ex2f(u2), ex2f(u3));

                // l accumulation on the tensor pipe (one issue slot)
                mma_f16(lac[f][0], lac[f][1], lac[f][2], lac[f][3], a0, a1, a2, a3, ones, ones);
                mma_f16(o[f][0], o[f][1], o[f][2], o[f][3], a0, a1, a2, a3, vv.x, vv.y);
                mma_f16(o[f][4], o[f][5], o[f][6], o[f][7], a0, a1, a2, a3, vv.z, vv.w);
            }
        }

        if (i + 2 < nstep && producer) {
            const size_t gb = (size_t)(kb0 + 2 * (i + 2)) * 32;
            const uint32_t sd = sdst + ((i + 2) % 3) * 192 * 16;
            cp_async16(sd,           gsrc + gb);
            cp_async16(sd + 96 * 16, gsrc + gb + 32);
        }
        CP_COMMIT();
    }

    const size_t pb = ((size_t)head * SPLIT + sp) * Ndim;
    #pragma unroll
    for (int f = 0; f < 2; f++) {
        const int rlo = qb + 16*f + g;
        const int rhi = rlo + 8;
        if (t == 0) {                       // col 0 of the ones-MMA = full row sum
            g_Pl[pb + rlo] = lac[f][0];
            g_Pl[pb + rhi] = lac[f][2];
        }
        #pragma unroll
        for (int c = 0; c < 2; c++) {
            const int d0 = 8 * c + 2 * t;
            *reinterpret_cast<float2*>(g_Po + (pb + rlo) * Ddim + d0) =
                make_float2(o[f][4*c+0], o[f][4*c+1]);
            *reinterpret_cast<float2*>(g_Po + (pb + rhi) * Ddim + d0) =
                make_float2(o[f][4*c+2], o[f][4*c+3]);
        }
    }
}

// ---------------------------------------------------------------------------
// Kernel 2b: combine — one thread per (head, n, d-quad), fully coalesced.
// ---------------------------------------------------------------------------
__global__ __launch_bounds__(128) void combine_kernel(const float* __restrict__ bt)
{
    const int idx  = blockIdx.x * 128 + threadIdx.x;
    const int head = idx >> 13;
    const int n    = (idx >> 2) & (Ndim - 1);
    const int quad = idx & 3;

    float L = 0.f;
    float4 o = make_float4(0.f, 0.f, 0.f, 0.f);
    #pragma unroll
    for (int s = 0; s < SPLIT; s++) {
        const size_t pb = ((size_t)head * SPLIT + s) * Ndim + n;
        L += g_Pl[pb];
        const float4 v = reinterpret_cast<const float4*>(g_Po)[pb * 4 + quad];
        o.x += v.x; o.y += v.y; o.z += v.z; o.w += v.w;
    }
    const float inv = 1.f / L;

    const int b = head >> 3, k = head & 7;
    const float4 bb = reinterpret_cast<const float4*>(bt)[k * 4 + quad];
    float4 r;
    r.x = o.x * inv + bb.x;
    r.y = o.y * inv + bb.y;
    r.z = o.z * inv + bb.z;
    r.w = o.w * inv + bb.w;
    reinterpret_cast<float4*>(g_O)[(((size_t)(b * Ndim + n)) * Kdim + k) * 4 + quad] = r;
}

// ---------------------------------------------------------------------------
// Kernel 3: output projection as fp16 hi/lo tensor-core GEMM.
// ---------------------------------------------------------------------------
__global__ __launch_bounds__(128) void out_kernel(float* __restrict__ out)
{
    const int row0 = blockIdx.x * 16;
    const int warp = threadIdx.x >> 5;
    const int lane = threadIdx.x & 31;
    const int g = lane >> 2, t = lane & 3;

    float acc[4][4];
    #pragma unroll
    for (int e4 = 0; e4 < 4; e4++)
        #pragma unroll
        for (int i = 0; i < 4; i++) acc[e4][i] = 0.f;

    const float* Orl = g_O + (size_t)(row0 + g    ) * 128;
    const float* Orh = g_O + (size_t)(row0 + g + 8) * 128;

    #pragma unroll
    for (int kc = 0; kc < 8; kc++) {
        const float2 xA = *reinterpret_cast<const float2*>(Orl + kc * 16 + 2 * t);
        const float2 yA = *reinterpret_cast<const float2*>(Orh + kc * 16 + 2 * t);
        const float2 xB = *reinterpret_cast<const float2*>(Orl + kc * 16 + 2 * t + 8);
        const float2 yB = *reinterpret_cast<const float2*>(Orh + kc * 16 + 2 * t + 8);
        const uint32_t ah0 = pack_h2(xA.x, xA.y), al0 = split_lo(xA.x, xA.y, ah0);
        const uint32_t ah1 = pack_h2(yA.x, yA.y), al1 = split_lo(yA.x, yA.y, ah1);
        const uint32_t ah2 = pack_h2(xB.x, xB.y), al2 = split_lo(xB.x, xB.y, ah2);
        const uint32_t ah3 = pack_h2(yB.x, yB.y), al3 = split_lo(yB.x, yB.y, ah3);

        #pragma unroll
        for (int e4 = 0; e4 < 4; e4++) {
            const uint4 wv = g_W[(kc * 16 + (warp * 4 + e4)) * 32 + lane];
            mma_f16(acc[e4][0], acc[e4][1], acc[e4][2], acc[e4][3], ah0, ah1, ah2, ah3, wv.x, wv.y);
            mma_f16(acc[e4][0], acc[e4][1], acc[e4][2], acc[e4][3], al0, al1, al2, al3, wv.x, wv.y);
            mma_f16(acc[e4][0], acc[e4][1], acc[e4][2], acc[e4][3], ah0, ah1, ah2, ah3, wv.z, wv.w);
        }
    }

    #pragma unroll
    for (int e4 = 0; e4 < 4; e4++) {
        const int e0 = (warp * 4 + e4) * 8 + 2 * t;
        *reinterpret_cast<float2*>(out + (size_t)(row0 + g    ) * Edim + e0) =
            make_float2(acc[e4][0], acc[e4][1]);
        *reinterpret_cast<float2*>(out + (size_t)(row0 + g + 8) * Edim + e0) =
            make_float2(acc[e4][2], acc[e4][3]);
    }
}

extern "C" void kernel_launch(void* const* d_in, const int* in_sizes, int n_in,
                              void* d_out, int out_size)
{
    const float* x  = (const float*)d_in[0];
    const float* y  = (const float*)d_in[1];
    const float* l1 = (const float*)d_in[2];
    const float* l2 = (const float*)d_in[3];
    const float* t1 = (const float*)d_in[4];
    const float* t2 = (const float*)d_in[5];
    const float* bl = (const float*)d_in[6];
    const float* bt = (const float*)d_in[7];

    prep_all<<<128, 128>>>(t2, l1, t1, l2);
    proj_mma<<<dim3(64, 4, 2), 128>>>(x, y, bl);
    flash_kernel<<<dim3(Ndim / 128, NHEAD, SPLIT), 128>>>();
    combine_kernel<<<NHEAD * Ndim * 4 / 128, 128>>>(bt);
    out_kernel<<<Bdim * Ndim / 16, 128>>>((float*)d_out);
}

// round 15
// speedup vs baseline: 1.2236x; 1.0517x over previous
#include <cuda_runtime.h>
#include <cuda_fp16.h>
#include <math.h>
#include <stdint.h>

// Problem dims (fixed)
#define Bdim 2
#define Mdim 2048
#define Ndim 2048
#define Edim 128
#define Kdim 8
#define Ddim 16
#define NHEAD (Bdim * Kdim)
#define SPLIT 4
#define MCHUNK (Mdim / SPLIT)   // 512 keys per split
#define SHIFT 10.0f             // uniform log2-domain logit shift (softmax-invariant)

// Static scratch (fragment-packed; uint4 = one warp-lane's fragment piece).
__device__ uint4 g_Qh[NHEAD * (size_t)(Ndim / 16) * 32];
__device__ uint4 g_Ql[NHEAD * (size_t)(Ndim / 16) * 32];
__device__ uint4 g_Kh[NHEAD * (size_t)(Mdim / 16) * 32];
__device__ uint4 g_Kl[NHEAD * (size_t)(Mdim / 16) * 32];
__device__ uint4 g_Vh[NHEAD * (size_t)(Mdim / 16) * 32];
__device__ uint4 g_WF[3 * 8 * 8 * 2 * 32];
__device__ uint4 g_W [8 * 16 * 32];
__device__ float g_Po[NHEAD * (size_t)SPLIT * Ndim * Ddim];
__device__ float g_Pl[NHEAD * (size_t)SPLIT * Ndim];

__device__ __forceinline__ float ex2f(float x) {
    float r; asm("ex2.approx.f32 %0, %1;" : "=f"(r) : "f"(x)); return r;
}
__device__ __forceinline__ uint32_t pack_h2(float a, float b) {
    __half2 h = __floats2half2_rn(a, b);
    return *reinterpret_cast<uint32_t*>(&h);
}
__device__ __forceinline__ float2 unpack_h2(uint32_t u) {
    __half2 h = *reinterpret_cast<__half2*>(&u);
    return __half22float2(h);
}
__device__ __forceinline__ uint32_t split_lo(float a, float b, uint32_t hi) {
    float2 hf = unpack_h2(hi);
    return pack_h2(a - hf.x, b - hf.y);
}
__device__ __forceinline__ uint32_t movm_t(uint32_t s) {
    uint32_t d;
    asm("movmatrix.sync.aligned.m8n8.trans.b16 %0, %1;" : "=r"(d) : "r"(s));
    return d;
}
__device__ __forceinline__ void cp_async16(uint32_t saddr, const void* g) {
    asm volatile("cp.async.cg.shared.global [%0], [%1], 16;" :: "r"(saddr), "l"(g));
}
#define CP_COMMIT() asm volatile("cp.async.commit_group;" ::: "memory")
#define CP_WAIT1()  asm volatile("cp.async.wait_group 1;" ::: "memory")

__device__ __forceinline__ void mma_f16(float& d0, float& d1, float& d2, float& d3,
                                        uint32_t a0, uint32_t a1, uint32_t a2, uint32_t a3,
                                        uint32_t b0, uint32_t b1) {
    asm volatile("mma.sync.aligned.m16n8k16.row.col.f32.f16.f16.f32 "
                 "{%0,%1,%2,%3},{%4,%5,%6,%7},{%8,%9},{%0,%1,%2,%3};"
                 : "+f"(d0), "+f"(d1), "+f"(d2), "+f"(d3)
                 : "r"(a0), "r"(a1), "r"(a2), "r"(a3), "r"(b0), "r"(b1));
}
__device__ __forceinline__ void mma_f16_c(float& d0, float& d1, float& d2, float& d3,
                                          uint32_t a0, uint32_t a1, uint32_t a2, uint32_t a3,
                                          uint32_t b0, uint32_t b1, float c) {
    asm volatile("mma.sync.aligned.m16n8k16.row.col.f32.f16.f16.f32 "
                 "{%0,%1,%2,%3},{%4,%5,%6,%7},{%8,%9},{%10,%10,%10,%10};"
                 : "=f"(d0), "=f"(d1), "=f"(d2), "=f"(d3)
                 : "r"(a0), "r"(a1), "r"(a2), "r"(a3), "r"(b0), "r"(b1), "f"(c));
}

// ---------------------------------------------------------------------------
// Kernel 0: merged weight prep. Blocks [0,32): theta2 -> g_W.
// Blocks [32,128): proj weights (l1, t1, l2*sc) -> g_WF.
// ---------------------------------------------------------------------------
__global__ __launch_bounds__(128) void prep_all(
    const float* __restrict__ t2,
    const float* __restrict__ l1, const float* __restrict__ t1,
    const float* __restrict__ l2)
{
    if (blockIdx.x < 32) {
        const int idx  = blockIdx.x * 128 + threadIdx.x;   // 0..4095
        const int kc   = idx >> 9;
        const int et   = (idx >> 5) & 15;
        const int lane = idx & 31;
        const int g = lane >> 2, t = lane & 3;
        const int e = et * 8 + g;

        const float2 wA = *reinterpret_cast<const float2*>(t2 + ((size_t)kc * Edim + e) * Ddim + 2 * t);
        const float2 wB = *reinterpret_cast<const float2*>(t2 + ((size_t)kc * Edim + e) * Ddim + 2 * t + 8);
        const uint32_t h0 = pack_h2(wA.x, wA.y), l0 = split_lo(wA.x, wA.y, h0);
        const uint32_t h1 = pack_h2(wB.x, wB.y), l1v = split_lo(wB.x, wB.y, h1);
        g_W[(kc * 16 + et) * 32 + lane] = make_uint4(h0, h1, l0, l1v);
    } else {
        const int idx  = (blockIdx.x - 32) * 128 + threadIdx.x;  // 0..12287
        const int lane = idx & 31;
        const int nt   = (idx >> 5) & 1;
        const int c    = (idx >> 6) & 7;
        const int k    = (idx >> 9) & 7;
        const int a    = idx >> 12;
        const int g = lane >> 2, t = lane & 3;

        const float* W = (a == 0) ? l1 : (a == 1) ? t1 : l2;
        const float s  = (a == 2) ? (0.25f * 1.4426950408889634f) : 1.0f;
        const int d  = nt * 8 + g;
        const int e0 = c * 16 + 2 * t;

        const float w00 = W[((size_t)k * Edim + e0    ) * Ddim + d] * s;
        const float w01 = W[((size_t)k * Edim + e0 + 1) * Ddim + d] * s;
        const float w10 = W[((size_t)k * Edim + e0 + 8) * Ddim + d] * s;
        const float w11 = W[((size_t)k * Edim + e0 + 9) * Ddim + d] * s;
        const uint32_t h0 = pack_h2(w00, w01), lo0 = split_lo(w00, w01, h0);
        const uint32_t h1 = pack_h2(w10, w11), lo1 = split_lo(w10, w11, h1);
        g_WF[((a * 8 + k) * 8 + c) * 64 + nt * 32 + lane] = make_uint4(h0, h1, lo0, lo1);
    }
}

// ---------------------------------------------------------------------------
// Kernel 1: projections as fp16 hi/lo MMA (3-pass Dekker), register-exact
// packing into the flash fragment layouts (K/Q: pair-pack; V: movmatrix).
// ---------------------------------------------------------------------------
__global__ __launch_bounds__(128) void proj_mma(
    const float* __restrict__ x, const float* __restrict__ y,
    const float* __restrict__ bl)
{
    const int warp = threadIdx.x >> 5;
    const int lane = threadIdx.x & 31;
    const int g = lane >> 2, t = lane & 3;
    const int tile = blockIdx.x * 4 + warp;
    const int hp   = blockIdx.y;
    const bool isQ = (blockIdx.z != 0);
    const int row0 = tile * 16;
    const int b    = row0 >> 11;
    const int m0   = row0 & (Mdim - 1);

    const float* src = isQ ? y : x;
    uint32_t ahi[8][4], alo[8][4];
    #pragma unroll
    for (int c = 0; c < 8; c++) {
        const float* base = src + (size_t)row0 * Edim + c * 16;
        const float2 v0 = *reinterpret_cast<const float2*>(base + (g    ) * Edim + 2 * t);
        const float2 v1 = *reinterpret_cast<const float2*>(base + (g + 8) * Edim + 2 * t);
        const float2 v2 = *reinterpret_cast<const float2*>(base + (g    ) * Edim + 2 * t + 8);
        const float2 v3 = *reinterpret_cast<const float2*>(base + (g + 8) * Edim + 2 * t + 8);
        ahi[c][0] = pack_h2(v0.x, v0.y); alo[c][0] = split_lo(v0.x, v0.y, ahi[c][0]);
        ahi[c][1] = pack_h2(v1.x, v1.y); alo[c][1] = split_lo(v1.x, v1.y, ahi[c][1]);
        ahi[c][2] = pack_h2(v2.x, v2.y); alo[c][2] = split_lo(v2.x, v2.y, ahi[c][2]);
        ahi[c][3] = pack_h2(v3.x, v3.y); alo[c][3] = split_lo(v3.x, v3.y, ahi[c][3]);
    }

    #pragma unroll
    for (int hh = 0; hh < 2; hh++) {
        const int k = hp * 2 + hh;
        const int head = b * Kdim + k;
        const size_t oidx = ((size_t)head * (Mdim / 16) + (m0 >> 4)) * 32 + lane;

        if (!isQ) {
            float cK[2][4], cV[2][4];
            #pragma unroll
            for (int nt = 0; nt < 2; nt++)
                #pragma unroll
                for (int i = 0; i < 4; i++) { cK[nt][i] = 0.f; cV[nt][i] = 0.f; }

            #pragma unroll
            for (int c = 0; c < 8; c++) {
                #pragma unroll
                for (int nt = 0; nt < 2; nt++) {
                    const uint4 wK = g_WF[((0 * 8 + k) * 8 + c) * 64 + nt * 32 + lane];
                    mma_f16(cK[nt][0], cK[nt][1], cK[nt][2], cK[nt][3],
                            ahi[c][0], ahi[c][1], ahi[c][2], ahi[c][3], wK.x, wK.y);
                    mma_f16(cK[nt][0], cK[nt][1], cK[nt][2], cK[nt][3],
                            alo[c][0], alo[c][1], alo[c][2], alo[c][3], wK.x, wK.y);
                    mma_f16(cK[nt][0], cK[nt][1], cK[nt][2], cK[nt][3],
                            ahi[c][0], ahi[c][1], ahi[c][2], ahi[c][3], wK.z, wK.w);
                    const uint4 wV = g_WF[((1 * 8 + k) * 8 + c) * 64 + nt * 32 + lane];
                    mma_f16(cV[nt][0], cV[nt][1], cV[nt][2], cV[nt][3],
                            ahi[c][0], ahi[c][1], ahi[c][2], ahi[c][3], wV.x, wV.y);
                    mma_f16(cV[nt][0], cV[nt][1], cV[nt][2], cV[nt][3],
                            alo[c][0], alo[c][1], alo[c][2], alo[c][3], wV.x, wV.y);
                    mma_f16(cV[nt][0], cV[nt][1], cV[nt][2], cV[nt][3],
                            ahi[c][0], ahi[c][1], ahi[c][2], ahi[c][3], wV.z, wV.w);
                }
            }

            const float2 bl0 = *reinterpret_cast<const float2*>(bl + k * Ddim + 2 * t);
            const float2 bl1 = *reinterpret_cast<const float2*>(bl + k * Ddim + 8 + 2 * t);
            cK[0][0] += bl0.x; cK[0][1] += bl0.y; cK[0][2] += bl0.x; cK[0][3] += bl0.y;
            cK[1][0] += bl1.x; cK[1][1] += bl1.y; cK[1][2] += bl1.x; cK[1][3] += bl1.y;

            uint4 kh, kl;
            kh.x = pack_h2(cK[0][0], cK[0][1]); kl.x = split_lo(cK[0][0], cK[0][1], kh.x);
            kh.y = pack_h2(cK[1][0], cK[1][1]); kl.y = split_lo(cK[1][0], cK[1][1], kh.y);
            kh.z = pack_h2(cK[0][2], cK[0][3]); kl.z = split_lo(cK[0][2], cK[0][3], kh.z);
            kh.w = pack_h2(cK[1][2], cK[1][3]); kl.w = split_lo(cK[1][2], cK[1][3], kh.w);
            g_Kh[oidx] = kh;
            g_Kl[oidx] = kl;

            uint4 vv;
            vv.x = movm_t(pack_h2(cV[0][0], cV[0][1]));
            vv.y = movm_t(pack_h2(cV[0][2], cV[0][3]));
            vv.z = movm_t(pack_h2(cV[1][0], cV[1][1]));
            vv.w = movm_t(pack_h2(cV[1][2], cV[1][3]));
            g_Vh[oidx] = vv;
        } else {
            float cQ[2][4];
            #pragma unroll
            for (int nt = 0; nt < 2; nt++)
                #pragma unroll
                for (int i = 0; i < 4; i++) cQ[nt][i] = 0.f;

            #pragma unroll
            for (int c = 0; c < 8; c++) {
                #pragma unroll
                for (int nt = 0; nt < 2; nt++) {
                    const uint4 wQ = g_WF[((2 * 8 + k) * 8 + c) * 64 + nt * 32 + lane];
                    mma_f16(cQ[nt][0], cQ[nt][1], cQ[nt][2], cQ[nt][3],
                            ahi[c][0], ahi[c][1], ahi[c][2], ahi[c][3], wQ.x, wQ.y);
                    mma_f16(cQ[nt][0], cQ[nt][1], cQ[nt][2], cQ[nt][3],
                            alo[c][0], alo[c][1], alo[c][2], alo[c][3], wQ.x, wQ.y);
                    mma_f16(cQ[nt][0], cQ[nt][1], cQ[nt][2], cQ[nt][3],
                            ahi[c][0], ahi[c][1], ahi[c][2], ahi[c][3], wQ.z, wQ.w);
                }
            }
            uint4 qh, ql;
            qh.x = pack_h2(cQ[0][0], cQ[0][1]); ql.x = split_lo(cQ[0][0], cQ[0][1], qh.x);
            qh.y = pack_h2(cQ[0][2], cQ[0][3]); ql.y = split_lo(cQ[0][2], cQ[0][3], qh.y);
            qh.z = pack_h2(cQ[1][0], cQ[1][1]); ql.z = split_lo(cQ[1][0], cQ[1][1], qh.z);
            qh.w = pack_h2(cQ[1][2], cQ[1][3]); ql.w = split_lo(cQ[1][2], cQ[1][3], qh.w);
            g_Qh[oidx] = qh;
            g_Ql[oidx] = ql;
        }
    }
}

// ---------------------------------------------------------------------------
// Kernel 2: flash attention, fp16 hi/lo mma, split-K, cp.async smem pipeline.
// Two key-tiles per pipeline stage (R14 best shape), ones-MMA lsum.
// ---------------------------------------------------------------------------
__global__ __launch_bounds__(128) void flash_kernel()
{
    __shared__ __align__(16) uint4 sbuf[3][192];  // [stage][tile*96 + arr*32 + lane]

    const int head = blockIdx.y;
    const int sp   = blockIdx.z;
    const int tid  = threadIdx.x;
    const int warp = tid >> 5;
    const int lane = tid & 31;
    const int g = lane >> 2, t = lane & 3;
    const int qb = blockIdx.x * 128 + warp * 32;

    uint4 qh[2], ql[2];
    #pragma unroll
    for (int f = 0; f < 2; f++) {
        const size_t qidx = ((size_t)head * (Ndim / 16) + (qb >> 4) + f) * 32 + lane;
        qh[f] = g_Qh[qidx];
        ql[f] = g_Ql[qidx];
    }

    const uint32_t ones = (g == 0) ? 0x3C003C00u : 0u;

    float o[2][8];
    float lac[2][4];
    #pragma unroll
    for (int f = 0; f < 2; f++) {
        #pragma unroll
        for (int i = 0; i < 8; i++) o[f][i] = 0.f;
        #pragma unroll
        for (int i = 0; i < 4; i++) lac[f][i] = 0.f;
    }

    const int kb0   = sp * (MCHUNK / 16);
    const int nstep = MCHUNK / 32;                 // 16 double-tile steps

    const size_t hb = (size_t)head * (Mdim / 16) * 32;
    const uint4* gsrc =
        (warp == 0) ? (g_Kh + hb + lane) :
        (warp == 1) ? (g_Kl + hb + lane) :
                      (g_Vh + hb + lane);
    const bool producer = (tid < 96);
    const uint32_t sdst = (uint32_t)__cvta_generic_to_shared(&sbuf[0][warp * 32 + lane]);

    if (producer) {
        cp_async16(sdst,                     gsrc + (size_t)(kb0    ) * 32);
        cp_async16(sdst + 96 * 16,           gsrc + (size_t)(kb0 + 1) * 32);
    }
    CP_COMMIT();
    if (producer) {
        cp_async16(sdst + 192 * 16,          gsrc + (size_t)(kb0 + 2) * 32);
        cp_async16(sdst + (192 + 96) * 16,   gsrc + (size_t)(kb0 + 3) * 32);
    }
    CP_COMMIT();

    #pragma unroll 2
    for (int i = 0; i < nstep; i++) {
        CP_WAIT1();
        __syncthreads();

        const int st = i % 3;
        #pragma unroll
        for (int j = 0; j < 2; j++) {
            const uint4 kh = sbuf[st][j * 96 + lane];
            const uint4 kl = sbuf[st][j * 96 + 32 + lane];
            const uint4 vv = sbuf[st][j * 96 + 64 + lane];

            #pragma unroll
            for (int f = 0; f < 2; f++) {
                float s0, s1, s2, s3;
                mma_f16_c(s0, s1, s2, s3, qh[f].x, qh[f].y, qh[f].z, qh[f].w, kh.x, kh.y, -SHIFT);
                mma_f16  (s0, s1, s2, s3, ql[f].x, ql[f].y, ql[f].z, ql[f].w, kh.x, kh.y);
                mma_f16  (s0, s1, s2, s3, qh[f].x, qh[f].y, qh[f].z, qh[f].w, kl.x, kl.y);
                float u0, u1, u2, u3;
                mma_f16_c(u0, u1, u2, u3, qh[f].x, qh[f].y, qh[f].z, qh[f].w, kh.z, kh.w, -SHIFT);
                mma_f16  (u0, u1, u2, u3, ql[f].x, ql[f].y, ql[f].z, ql[f].w, kh.z, kh.w);
                mma_f16  (u0, u1, u2, u3, qh[f].x, qh[f].y, qh[f].z, qh[f].w, kl.z, kl.w);

                const uint32_t a0 = pack_h2(ex2f(s0), ex2f(s1));
                const uint32_t a1 = pack_h2(ex2f(s2), ex2f(s3));
                const uint32_t a2 = pack_h2(ex2f(u0), ex2f(u1));
                const uint32_t a3 = pack_h2(ex2f(u2), ex2f(u3));

                mma_f16(lac[f][0], lac[f][1], lac[f][2], lac[f][3], a0, a1, a2, a3, ones, ones);
                mma_f16(o[f][0], o[f][1], o[f][2], o[f][3], a0, a1, a2, a3, vv.x, vv.y);
                mma_f16(o[f][4], o[f][5], o[f][6], o[f][7], a0, a1, a2, a3, vv.z, vv.w);
            }
        }

        if (i + 2 < nstep && producer) {
            const size_t gb = (size_t)(kb0 + 2 * (i + 2)) * 32;
            const uint32_t sd = sdst + ((i + 2) % 3) * 192 * 16;
            cp_async16(sd,           gsrc + gb);
            cp_async16(sd + 96 * 16, gsrc + gb + 32);
        }
        CP_COMMIT();
    }

    const size_t pb = ((size_t)head * SPLIT + sp) * Ndim;
    #pragma unroll
    for (int f = 0; f < 2; f++) {
        const int rlo = qb + 16*f + g;
        const int rhi = rlo + 8;
        if (t == 0) {
            g_Pl[pb + rlo] = lac[f][0];
            g_Pl[pb + rhi] = lac[f][2];
        }
        #pragma unroll
        for (int c = 0; c < 2; c++) {
            const int d0 = 8 * c + 2 * t;
            *reinterpret_cast<float2*>(g_Po + (pb + rlo) * Ddim + d0) =
                make_float2(o[f][4*c+0], o[f][4*c+1]);
            *reinterpret_cast<float2*>(g_Po + (pb + rhi) * Ddim + d0) =
                make_float2(o[f][4*c+2], o[f][4*c+3]);
        }
    }
}

// ---------------------------------------------------------------------------
// Kernel 3: FUSED combine + output projection.
// Phase 1: combine split partials (normalize + bias) into an smem O-tile.
// Phase 2: fp16 hi/lo tensor-core GEMM against theta2, A from smem.
// smem row stride padded to 132 floats to avoid 8-way LDS bank conflicts.
// ---------------------------------------------------------------------------
__global__ __launch_bounds__(128) void out_kernel(const float* __restrict__ bt,
                                                  float* __restrict__ out)
{
    __shared__ float sO[16][132];
    __shared__ float sInv[16][8];

    const int row0 = blockIdx.x * 16;
    const int b    = row0 >> 11;
    const int n0   = row0 & (Ndim - 1);
    const int tid  = threadIdx.x;
    const int warp = tid >> 5;
    const int lane = tid & 31;
    const int g = lane >> 2, t = lane & 3;

    // Phase 1a: 1/L per (row, k) — one thread each.
    {
        const int r = tid >> 3, k = tid & 7;
        const int head = b * Kdim + k;
        float L = 0.f;
        #pragma unroll
        for (int s = 0; s < SPLIT; s++)
            L += g_Pl[((size_t)head * SPLIT + s) * Ndim + n0 + r];
        sInv[r][k] = 1.f / L;
    }
    __syncthreads();

    // Phase 1b: combined O tile -> smem. 512 float4-tasks, 4 per thread.
    #pragma unroll
    for (int it = 0; it < 4; it++) {
        const int task = tid + it * 128;        // 0..511
        const int quad = task & 3;
        const int k    = (task >> 2) & 7;
        const int r    = task >> 5;
        const int head = b * Kdim + k;
        float4 o = make_float4(0.f, 0.f, 0.f, 0.f);
        #pragma unroll
        for (int s = 0; s < SPLIT; s++) {
            const float4 v = *reinterpret_cast<const float4*>(
                g_Po + (((size_t)head * SPLIT + s) * Ndim + n0 + r) * Ddim + quad * 4);
            o.x += v.x; o.y += v.y; o.z += v.z; o.w += v.w;
        }
        const float inv = sInv[r][k];
        const float4 bb = reinterpret_cast<const float4*>(bt)[k * 4 + quad];
        float* dst = &sO[r][k * 16 + quad * 4];
        dst[0] = o.x * inv + bb.x;
        dst[1] = o.y * inv + bb.y;
        dst[2] = o.z * inv + bb.z;
        dst[3] = o.w * inv + bb.w;
    }
    __syncthreads();

    // Phase 2: GEMM from smem A-tile.
    float acc[4][4];
    #pragma unroll
    for (int e4 = 0; e4 < 4; e4++)
        #pragma unroll
        for (int i = 0; i < 4; i++) acc[e4][i] = 0.f;

    const float* Orl = &sO[g][0];
    const float* Orh = &sO[g + 8][0];

    #pragma unroll
    for (int kc = 0; kc < 8; kc++) {
        const float2 xA = *reinterpret_cast<const float2*>(Orl + kc * 16 + 2 * t);
        const float2 yA = *reinterpret_cast<const float2*>(Orh + kc * 16 + 2 * t);
        const float2 xB = *reinterpret_cast<const float2*>(Orl + kc * 16 + 2 * t + 8);
        const float2 yB = *reinterpret_cast<const float2*>(Orh + kc * 16 + 2 * t + 8);
        const uint32_t ah0 = pack_h2(xA.x, xA.y), al0 = split_lo(xA.x, xA.y, ah0);
        const uint32_t ah1 = pack_h2(yA.x, yA.y), al1 = split_lo(yA.x, yA.y, ah1);
        const uint32_t ah2 = pack_h2(xB.x, xB.y), al2 = split_lo(xB.x, xB.y, ah2);
        const uint32_t ah3 = pack_h2(yB.x, yB.y), al3 = split_lo(yB.x, yB.y, ah3);

        #pragma unroll
        for (int e4 = 0; e4 < 4; e4++) {
            const uint4 wv = g_W[(kc * 16 + (warp * 4 + e4)) * 32 + lane];
            mma_f16(acc[e4][0], acc[e4][1], acc[e4][2], acc[e4][3], ah0, ah1, ah2, ah3, wv.x, wv.y);
            mma_f16(acc[e4][0], acc[e4][1], acc[e4][2], acc[e4][3], al0, al1, al2, al3, wv.x, wv.y);
            mma_f16(acc[e4][0], acc[e4][1], acc[e4][2], acc[e4][3], ah0, ah1, ah2, ah3, wv.z, wv.w);
        }
    }

    #pragma unroll
    for (int e4 = 0; e4 < 4; e4++) {
        const int e0 = (warp * 4 + e4) * 8 + 2 * t;
        *reinterpret_cast<float2*>(out + (size_t)(row0 + g    ) * Edim + e0) =
            make_float2(acc[e4][0], acc[e4][1]);
        *reinterpret_cast<float2*>(out + (size_t)(row0 + g + 8) * Edim + e0) =
            make_float2(acc[e4][2], acc[e4][3]);
    }
}

extern "C" void kernel_launch(void* const* d_in, const int* in_sizes, int n_in,
                              void* d_out, int out_size)
{
    const float* x  = (const float*)d_in[0];
    const float* y  = (const float*)d_in[1];
    const float* l1 = (const float*)d_in[2];
    const float* l2 = (const float*)d_in[3];
    const float* t1 = (const float*)d_in[4];
    const float* t2 = (const float*)d_in[5];
    const float* bl = (const float*)d_in[6];
    const float* bt = (const float*)d_in[7];

    prep_all<<<128, 128>>>(t2, l1, t1, l2);
    proj_mma<<<dim3(64, 4, 2), 128>>>(x, y, bl);
    flash_kernel<<<dim3(Ndim / 128, NHEAD, SPLIT), 128>>>();
    out_kernel<<<Bdim * Ndim / 16, 128>>>(bt, (float*)d_out);
}

// round 16
// speedup vs baseline: 1.2418x; 1.0149x over previous
#include <cuda_runtime.h>
#include <cuda_fp16.h>
#include <math.h>
#include <stdint.h>

// Problem dims (fixed)
#define Bdim 2
#define Mdim 2048
#define Ndim 2048
#define Edim 128
#define Kdim 8
#define Ddim 16
#define NHEAD (Bdim * Kdim)
#define SPLIT 4
#define MCHUNK (Mdim / SPLIT)   // 512 keys per split
#define SHIFT 10.0f             // uniform log2-domain logit shift (softmax-invariant)

// Static scratch (fragment-packed; uint4 = one warp-lane's fragment piece).
__device__ uint4 g_Qh[NHEAD * (size_t)(Ndim / 16) * 32];
__device__ uint4 g_Ql[NHEAD * (size_t)(Ndim / 16) * 32];
__device__ uint4 g_Kh[NHEAD * (size_t)(Mdim / 16) * 32];
__device__ uint4 g_Kl[NHEAD * (size_t)(Mdim / 16) * 32];
__device__ uint4 g_Vh[NHEAD * (size_t)(Mdim / 16) * 32];
__device__ uint4 g_WF[3 * 8 * 8 * 2 * 32];
__device__ uint4 g_W [8 * 16 * 32];
__device__ float g_Po[NHEAD * (size_t)SPLIT * Ndim * Ddim];
__device__ float g_Pl[NHEAD * (size_t)SPLIT * Ndim];

__device__ __forceinline__ float ex2f(float x) {
    float r; asm("ex2.approx.f32 %0, %1;" : "=f"(r) : "f"(x)); return r;
}
__device__ __forceinline__ uint32_t pack_h2(float a, float b) {
    __half2 h = __floats2half2_rn(a, b);
    return *reinterpret_cast<uint32_t*>(&h);
}
__device__ __forceinline__ float2 unpack_h2(uint32_t u) {
    __half2 h = *reinterpret_cast<__half2*>(&u);
    return __half22float2(h);
}
__device__ __forceinline__ uint32_t split_lo(float a, float b, uint32_t hi) {
    float2 hf = unpack_h2(hi);
    return pack_h2(a - hf.x, b - hf.y);
}
__device__ __forceinline__ uint32_t movm_t(uint32_t s) {
    uint32_t d;
    asm("movmatrix.sync.aligned.m8n8.trans.b16 %0, %1;" : "=r"(d) : "r"(s));
    return d;
}
__device__ __forceinline__ void cp_async16(uint32_t saddr, const void* g) {
    asm volatile("cp.async.cg.shared.global [%0], [%1], 16;" :: "r"(saddr), "l"(g));
}
#define CP_COMMIT() asm volatile("cp.async.commit_group;" ::: "memory")
#define CP_WAIT1()  asm volatile("cp.async.wait_group 1;" ::: "memory")

__device__ __forceinline__ void mma_f16(float& d0, float& d1, float& d2, float& d3,
                                        uint32_t a0, uint32_t a1, uint32_t a2, uint32_t a3,
                                        uint32_t b0, uint32_t b1) {
    asm volatile("mma.sync.aligned.m16n8k16.row.col.f32.f16.f16.f32 "
                 "{%0,%1,%2,%3},{%4,%5,%6,%7},{%8,%9},{%0,%1,%2,%3};"
                 : "+f"(d0), "+f"(d1), "+f"(d2), "+f"(d3)
                 : "r"(a0), "r"(a1), "r"(a2), "r"(a3), "r"(b0), "r"(b1));
}
__device__ __forceinline__ void mma_f16_c(float& d0, float& d1, float& d2, float& d3,
                                          uint32_t a0, uint32_t a1, uint32_t a2, uint32_t a3,
                                          uint32_t b0, uint32_t b1, float c) {
    asm volatile("mma.sync.aligned.m16n8k16.row.col.f32.f16.f16.f32 "
                 "{%0,%1,%2,%3},{%4,%5,%6,%7},{%8,%9},{%10,%10,%10,%10};"
                 : "=f"(d0), "=f"(d1), "=f"(d2), "=f"(d3)
                 : "r"(a0), "r"(a1), "r"(a2), "r"(a3), "r"(b0), "r"(b1), "f"(c));
}

// ---------------------------------------------------------------------------
// Kernel 0: merged weight prep. Blocks [0,32): theta2 -> g_W.
// Blocks [32,128): proj weights (l1, t1, l2*sc) -> g_WF.
// ---------------------------------------------------------------------------
__global__ __launch_bounds__(128) void prep_all(
    const float* __restrict__ t2,
    const float* __restrict__ l1, const float* __restrict__ t1,
    const float* __restrict__ l2)
{
    if (blockIdx.x < 32) {
        const int idx  = blockIdx.x * 128 + threadIdx.x;   // 0..4095
        const int kc   = idx >> 9;
        const int et   = (idx >> 5) & 15;
        const int lane = idx & 31;
        const int g = lane >> 2, t = lane & 3;
        const int e = et * 8 + g;

        const float2 wA = *reinterpret_cast<const float2*>(t2 + ((size_t)kc * Edim + e) * Ddim + 2 * t);
        const float2 wB = *reinterpret_cast<const float2*>(t2 + ((size_t)kc * Edim + e) * Ddim + 2 * t + 8);
        const uint32_t h0 = pack_h2(wA.x, wA.y), l0 = split_lo(wA.x, wA.y, h0);
        const uint32_t h1 = pack_h2(wB.x, wB.y), l1v = split_lo(wB.x, wB.y, h1);
        g_W[(kc * 16 + et) * 32 + lane] = make_uint4(h0, h1, l0, l1v);
    } else {
        const int idx  = (blockIdx.x - 32) * 128 + threadIdx.x;  // 0..12287
        const int lane = idx & 31;
        const int nt   = (idx >> 5) & 1;
        const int c    = (idx >> 6) & 7;
        const int k    = (idx >> 9) & 7;
        const int a    = idx >> 12;
        const int g = lane >> 2, t = lane & 3;

        const float* W = (a == 0) ? l1 : (a == 1) ? t1 : l2;
        const float s  = (a == 2) ? (0.25f * 1.4426950408889634f) : 1.0f;
        const int d  = nt * 8 + g;
        const int e0 = c * 16 + 2 * t;

        const float w00 = W[((size_t)k * Edim + e0    ) * Ddim + d] * s;
        const float w01 = W[((size_t)k * Edim + e0 + 1) * Ddim + d] * s;
        const float w10 = W[((size_t)k * Edim + e0 + 8) * Ddim + d] * s;
        const float w11 = W[((size_t)k * Edim + e0 + 9) * Ddim + d] * s;
        const uint32_t h0 = pack_h2(w00, w01), lo0 = split_lo(w00, w01, h0);
        const uint32_t h1 = pack_h2(w10, w11), lo1 = split_lo(w10, w11, h1);
        g_WF[((a * 8 + k) * 8 + c) * 64 + nt * 32 + lane] = make_uint4(h0, h1, lo0, lo1);
    }
}

// ---------------------------------------------------------------------------
// Kernel 1: projections as fp16 hi/lo MMA (3-pass Dekker), register-exact
// packing into the flash fragment layouts (K/Q: pair-pack; V: movmatrix).
// ---------------------------------------------------------------------------
__global__ __launch_bounds__(128) void proj_mma(
    const float* __restrict__ x, const float* __restrict__ y,
    const float* __restrict__ bl)
{
    const int warp = threadIdx.x >> 5;
    const int lane = threadIdx.x & 31;
    const int g = lane >> 2, t = lane & 3;
    const int tile = blockIdx.x * 4 + warp;
    const int hp   = blockIdx.y;
    const bool isQ = (blockIdx.z != 0);
    const int row0 = tile * 16;
    const int b    = row0 >> 11;
    const int m0   = row0 & (Mdim - 1);

    const float* src = isQ ? y : x;
    uint32_t ahi[8][4], alo[8][4];
    #pragma unroll
    for (int c = 0; c < 8; c++) {
        const float* base = src + (size_t)row0 * Edim + c * 16;
        const float2 v0 = *reinterpret_cast<const float2*>(base + (g    ) * Edim + 2 * t);
        const float2 v1 = *reinterpret_cast<const float2*>(base + (g + 8) * Edim + 2 * t);
        const float2 v2 = *reinterpret_cast<const float2*>(base + (g    ) * Edim + 2 * t + 8);
        const float2 v3 = *reinterpret_cast<const float2*>(base + (g + 8) * Edim + 2 * t + 8);
        ahi[c][0] = pack_h2(v0.x, v0.y); alo[c][0] = split_lo(v0.x, v0.y, ahi[c][0]);
        ahi[c][1] = pack_h2(v1.x, v1.y); alo[c][1] = split_lo(v1.x, v1.y, ahi[c][1]);
        ahi[c][2] = pack_h2(v2.x, v2.y); alo[c][2] = split_lo(v2.x, v2.y, ahi[c][2]);
        ahi[c][3] = pack_h2(v3.x, v3.y); alo[c][3] = split_lo(v3.x, v3.y, ahi[c][3]);
    }

    #pragma unroll
    for (int hh = 0; hh < 2; hh++) {
        const int k = hp * 2 + hh;
        const int head = b * Kdim + k;
        const size_t oidx = ((size_t)head * (Mdim / 16) + (m0 >> 4)) * 32 + lane;

        if (!isQ) {
            float cK[2][4], cV[2][4];
            #pragma unroll
            for (int nt = 0; nt < 2; nt++)
                #pragma unroll
                for (int i = 0; i < 4; i++) { cK[nt][i] = 0.f; cV[nt][i] = 0.f; }

            #pragma unroll
            for (int c = 0; c < 8; c++) {
                #pragma unroll
                for (int nt = 0; nt < 2; nt++) {
                    const uint4 wK = g_WF[((0 * 8 + k) * 8 + c) * 64 + nt * 32 + lane];
                    mma_f16(cK[nt][0], cK[nt][1], cK[nt][2], cK[nt][3],
                            ahi[c][0], ahi[c][1], ahi[c][2], ahi[c][3], wK.x, wK.y);
                    mma_f16(cK[nt][0], cK[nt][1], cK[nt][2], cK[nt][3],
                            alo[c][0], alo[c][1], alo[c][2], alo[c][3], wK.x, wK.y);
                    mma_f16(cK[nt][0], cK[nt][1], cK[nt][2], cK[nt][3],
                            ahi[c][0], ahi[c][1], ahi[c][2], ahi[c][3], wK.z, wK.w);
                    const uint4 wV = g_WF[((1 * 8 + k) * 8 + c) * 64 + nt * 32 + lane];
                    mma_f16(cV[nt][0], cV[nt][1], cV[nt][2], cV[nt][3],
                            ahi[c][0], ahi[c][1], ahi[c][2], ahi[c][3], wV.x, wV.y);
                    mma_f16(cV[nt][0], cV[nt][1], cV[nt][2], cV[nt][3],
                            alo[c][0], alo[c][1], alo[c][2], alo[c][3], wV.x, wV.y);
                    mma_f16(cV[nt][0], cV[nt][1], cV[nt][2], cV[nt][3],
                            ahi[c][0], ahi[c][1], ahi[c][2], ahi[c][3], wV.z, wV.w);
                }
            }

            const float2 bl0 = *reinterpret_cast<const float2*>(bl + k * Ddim + 2 * t);
            const float2 bl1 = *reinterpret_cast<const float2*>(bl + k * Ddim + 8 + 2 * t);
            cK[0][0] += bl0.x; cK[0][1] += bl0.y; cK[0][2] += bl0.x; cK[0][3] += bl0.y;
            cK[1][0] += bl1.x; cK[1][1] += bl1.y; cK[1][2] += bl1.x; cK[1][3] += bl1.y;

            uint4 kh, kl;
            kh.x = pack_h2(cK[0][0], cK[0][1]); kl.x = split_lo(cK[0][0], cK[0][1], kh.x);
            kh.y = pack_h2(cK[1][0], cK[1][1]); kl.y = split_lo(cK[1][0], cK[1][1], kh.y);
            kh.z = pack_h2(cK[0][2], cK[0][3]); kl.z = split_lo(cK[0][2], cK[0][3], kh.z);
            kh.w = pack_h2(cK[1][2], cK[1][3]); kl.w = split_lo(cK[1][2], cK[1][3], kh.w);
            g_Kh[oidx] = kh;
            g_Kl[oidx] = kl;

            uint4 vv;
            vv.x = movm_t(pack_h2(cV[0][0], cV[0][1]));
            vv.y = movm_t(pack_h2(cV[0][2], cV[0][3]));
            vv.z = movm_t(pack_h2(cV[1][0], cV[1][1]));
            vv.w = movm_t(pack_h2(cV[1][2], cV[1][3]));
            g_Vh[oidx] = vv;
        } else {
            float cQ[2][4];
            #pragma unroll
            for (int nt = 0; nt < 2; nt++)
                #pragma unroll
                for (int i = 0; i < 4; i++) cQ[nt][i] = 0.f;

            #pragma unroll
            for (int c = 0; c < 8; c++) {
                #pragma unroll
                for (int nt = 0; nt < 2; nt++) {
                    const uint4 wQ = g_WF[((2 * 8 + k) * 8 + c) * 64 + nt * 32 + lane];
                    mma_f16(cQ[nt][0], cQ[nt][1], cQ[nt][2], cQ[nt][3],
                            ahi[c][0], ahi[c][1], ahi[c][2], ahi[c][3], wQ.x, wQ.y);
                    mma_f16(cQ[nt][0], cQ[nt][1], cQ[nt][2], cQ[nt][3],
                            alo[c][0], alo[c][1], alo[c][2], alo[c][3], wQ.x, wQ.y);
                    mma_f16(cQ[nt][0], cQ[nt][1], cQ[nt][2], cQ[nt][3],
                            ahi[c][0], ahi[c][1], ahi[c][2], ahi[c][3], wQ.z, wQ.w);
                }
            }
            uint4 qh, ql;
            qh.x = pack_h2(cQ[0][0], cQ[0][1]); ql.x = split_lo(cQ[0][0], cQ[0][1], qh.x);
            qh.y = pack_h2(cQ[0][2], cQ[0][3]); ql.y = split_lo(cQ[0][2], cQ[0][3], qh.y);
            qh.z = pack_h2(cQ[1][0], cQ[1][1]); ql.z = split_lo(cQ[1][0], cQ[1][1], qh.z);
            qh.w = pack_h2(cQ[1][2], cQ[1][3]); ql.w = split_lo(cQ[1][2], cQ[1][3], qh.w);
            g_Qh[oidx] = qh;
            g_Ql[oidx] = ql;
        }
    }
}

// ---------------------------------------------------------------------------
// Kernel 2: flash attention, fp16 hi/lo mma, split-K, cp.async smem pipeline.
// Two key-tiles per pipeline stage (best measured shape), ones-MMA lsum.
// ---------------------------------------------------------------------------
__global__ __launch_bounds__(128) void flash_kernel()
{
    __shared__ __align__(16) uint4 sbuf[3][192];  // [stage][tile*96 + arr*32 + lane]

    const int head = blockIdx.y;
    const int sp   = blockIdx.z;
    const int tid  = threadIdx.x;
    const int warp = tid >> 5;
    const int lane = tid & 31;
    const int g = lane >> 2, t = lane & 3;
    const int qb = blockIdx.x * 128 + warp * 32;

    uint4 qh[2], ql[2];
    #pragma unroll
    for (int f = 0; f < 2; f++) {
        const size_t qidx = ((size_t)head * (Ndim / 16) + (qb >> 4) + f) * 32 + lane;
        qh[f] = g_Qh[qidx];
        ql[f] = g_Ql[qidx];
    }

    const uint32_t ones = (g == 0) ? 0x3C003C00u : 0u;

    float o[2][8];
    float lac[2][4];
    #pragma unroll
    for (int f = 0; f < 2; f++) {
        #pragma unroll
        for (int i = 0; i < 8; i++) o[f][i] = 0.f;
        #pragma unroll
        for (int i = 0; i < 4; i++) lac[f][i] = 0.f;
    }

    const int kb0   = sp * (MCHUNK / 16);
    const int nstep = MCHUNK / 32;                 // 16 double-tile steps

    const size_t hb = (size_t)head * (Mdim / 16) * 32;
    const uint4* gsrc =
        (warp == 0) ? (g_Kh + hb + lane) :
        (warp == 1) ? (g_Kl + hb + lane) :
                      (g_Vh + hb + lane);
    const bool producer = (tid < 96);
    const uint32_t sdst = (uint32_t)__cvta_generic_to_shared(&sbuf[0][warp * 32 + lane]);

    if (producer) {
        cp_async16(sdst,                     gsrc + (size_t)(kb0    ) * 32);
        cp_async16(sdst + 96 * 16,           gsrc + (size_t)(kb0 + 1) * 32);
    }
    CP_COMMIT();
    if (producer) {
        cp_async16(sdst + 192 * 16,          gsrc + (size_t)(kb0 + 2) * 32);
        cp_async16(sdst + (192 + 96) * 16,   gsrc + (size_t)(kb0 + 3) * 32);
    }
    CP_COMMIT();

    #pragma unroll 2
    for (int i = 0; i < nstep; i++) {
        CP_WAIT1();
        __syncthreads();

        const int st = i % 3;
        #pragma unroll
        for (int j = 0; j < 2; j++) {
            const uint4 kh = sbuf[st][j * 96 + lane];
            const uint4 kl = sbuf[st][j * 96 + 32 + lane];
            const uint4 vv = sbuf[st][j * 96 + 64 + lane];

            #pragma unroll
            for (int f = 0; f < 2; f++) {
                float s0, s1, s2, s3;
                mma_f16_c(s0, s1, s2, s3, qh[f].x, qh[f].y, qh[f].z, qh[f].w, kh.x, kh.y, -SHIFT);
                mma_f16  (s0, s1, s2, s3, ql[f].x, ql[f].y, ql[f].z, ql[f].w, kh.x, kh.y);
                mma_f16  (s0, s1, s2, s3, qh[f].x, qh[f].y, qh[f].z, qh[f].w, kl.x, kl.y);
                float u0, u1, u2, u3;
                mma_f16_c(u0, u1, u2, u3, qh[f].x, qh[f].y, qh[f].z, qh[f].w, kh.z, kh.w, -SHIFT);
                mma_f16  (u0, u1, u2, u3, ql[f].x, ql[f].y, ql[f].z, ql[f].w, kh.z, kh.w);
                mma_f16  (u0, u1, u2, u3, qh[f].x, qh[f].y, qh[f].z, qh[f].w, kl.z, kl.w);

                const uint32_t a0 = pack_h2(ex2f(s0), ex2f(s1));
                const uint32_t a1 = pack_h2(ex2f(s2), ex2f(s3));
                const uint32_t a2 = pack_h2(ex2f(u0), ex2f(u1));
                const uint32_t a3 = pack_h2(ex2f(u2), ex2f(u3));

                mma_f16(lac[f][0], lac[f][1], lac[f][2], lac[f][3], a0, a1, a2, a3, ones, ones);
                mma_f16(o[f][0], o[f][1], o[f][2], o[f][3], a0, a1, a2, a3, vv.x, vv.y);
                mma_f16(o[f][4], o[f][5], o[f][6], o[f][7], a0, a1, a2, a3, vv.z, vv.w);
            }
        }

        if (i + 2 < nstep && producer) {
            const size_t gb = (size_t)(kb0 + 2 * (i + 2)) * 32;
            const uint32_t sd = sdst + ((i + 2) % 3) * 192 * 16;
            cp_async16(sd,           gsrc + gb);
            cp_async16(sd + 96 * 16, gsrc + gb + 32);
        }
        CP_COMMIT();
    }

    const size_t pb = ((size_t)head * SPLIT + sp) * Ndim;
    #pragma unroll
    for (int f = 0; f < 2; f++) {
        const int rlo = qb + 16*f + g;
        const int rhi = rlo + 8;
        if (t == 0) {
            g_Pl[pb + rlo] = lac[f][0];
            g_Pl[pb + rhi] = lac[f][2];
        }
        #pragma unroll
        for (int c = 0; c < 2; c++) {
            const int d0 = 8 * c + 2 * t;
            *reinterpret_cast<float2*>(g_Po + (pb + rlo) * Ddim + d0) =
                make_float2(o[f][4*c+0], o[f][4*c+1]);
            *reinterpret_cast<float2*>(g_Po + (pb + rhi) * Ddim + d0) =
                make_float2(o[f][4*c+2], o[f][4*c+3]);
        }
    }
}

// ---------------------------------------------------------------------------
// Kernel 3: FUSED combine + output projection, 256 threads (8 warps).
// Phase 1: combine split partials (normalize + bias) into an smem O-tile.
// Phase 2: fp16 hi/lo GEMM; warp w covers e-tiles 2w..2w+1 (8 warps).
// ---------------------------------------------------------------------------
__global__ __launch_bounds__(256) void out_kernel(const float* __restrict__ bt,
                                                  float* __restrict__ out)
{
    __shared__ float sO[16][132];
    __shared__ float sInv[16][8];

    const int row0 = blockIdx.x * 16;
    const int b    = row0 >> 11;
    const int n0   = row0 & (Ndim - 1);
    const int tid  = threadIdx.x;
    const int warp = tid >> 5;
    const int lane = tid & 31;
    const int g = lane >> 2, t = lane & 3;

    // Phase 1a: 1/L per (row, k) — threads 0..127.
    if (tid < 128) {
        const int r = tid >> 3, k = tid & 7;
        const int head = b * Kdim + k;
        float L = 0.f;
        #pragma unroll
        for (int s = 0; s < SPLIT; s++)
            L += g_Pl[((size_t)head * SPLIT + s) * Ndim + n0 + r];
        sInv[r][k] = 1.f / L;
    }
    __syncthreads();

    // Phase 1b: combined O tile -> smem. 512 float4-tasks, 2 per thread.
    #pragma unroll
    for (int it = 0; it < 2; it++) {
        const int task = tid + it * 256;        // 0..511
        const int quad = task & 3;
        const int k    = (task >> 2) & 7;
        const int r    = task >> 5;
        const int head = b * Kdim + k;
        float4 o = make_float4(0.f, 0.f, 0.f, 0.f);
        #pragma unroll
        for (int s = 0; s < SPLIT; s++) {
            const float4 v = *reinterpret_cast<const float4*>(
                g_Po + (((size_t)head * SPLIT + s) * Ndim + n0 + r) * Ddim + quad * 4);
            o.x += v.x; o.y += v.y; o.z += v.z; o.w += v.w;
        }
        const float inv = sInv[r][k];
        const float4 bb = reinterpret_cast<const float4*>(bt)[k * 4 + quad];
        float* dst = &sO[r][k * 16 + quad * 4];
        dst[0] = o.x * inv + bb.x;
        dst[1] = o.y * inv + bb.y;
        dst[2] = o.z * inv + bb.z;
        dst[3] = o.w * inv + bb.w;
    }
    __syncthreads();

    // Phase 2: GEMM from smem A-tile; warp covers e-tiles 2*warp..2*warp+1.
    float acc[2][4];
    #pragma unroll
    for (int e4 = 0; e4 < 2; e4++)
        #pragma unroll
        for (int i = 0; i < 4; i++) acc[e4][i] = 0.f;

    const float* Orl = &sO[g][0];
    const float* Orh = &sO[g + 8][0];

    #pragma unroll
    for (int kc = 0; kc < 8; kc++) {
        const float2 xA = *reinterpret_cast<const float2*>(Orl + kc * 16 + 2 * t);
        const float2 yA = *reinterpret_cast<const float2*>(Orh + kc * 16 + 2 * t);
        const float2 xB = *reinterpret_cast<const float2*>(Orl + kc * 16 + 2 * t + 8);
        const float2 yB = *reinterpret_cast<const float2*>(Orh + kc * 16 + 2 * t + 8);
        const uint32_t ah0 = pack_h2(xA.x, xA.y), al0 = split_lo(xA.x, xA.y, ah0);
        const uint32_t ah1 = pack_h2(yA.x, yA.y), al1 = split_lo(yA.x, yA.y, ah1);
        const uint32_t ah2 = pack_h2(xB.x, xB.y), al2 = split_lo(xB.x, xB.y, ah2);
        const uint32_t ah3 = pack_h2(yB.x, yB.y), al3 = split_lo(yB.x, yB.y, ah3);

        #pragma unroll
        for (int e4 = 0; e4 < 2; e4++) {
            const uint4 wv = g_W[(kc * 16 + (warp * 2 + e4)) * 32 + lane];
            mma_f16(acc[e4][0], acc[e4][1], acc[e4][2], acc[e4][3], ah0, ah1, ah2, ah3, wv.x, wv.y);
            mma_f16(acc[e4][0], acc[e4][1], acc[e4][2], acc[e4][3], al0, al1, al2, al3, wv.x, wv.y);
            mma_f16(acc[e4][0], acc[e4][1], acc[e4][2], acc[e4][3], ah0, ah1, ah2, ah3, wv.z, wv.w);
        }
    }

    #pragma unroll
    for (int e4 = 0; e4 < 2; e4++) {
        const int e0 = (warp * 2 + e4) * 8 + 2 * t;
        *reinterpret_cast<float2*>(out + (size_t)(row0 + g    ) * Edim + e0) =
            make_float2(acc[e4][0], acc[e4][1]);
        *reinterpret_cast<float2*>(out + (size_t)(row0 + g + 8) * Edim + e0) =
            make_float2(acc[e4][2], acc[e4][3]);
    }
}

extern "C" void kernel_launch(void* const* d_in, const int* in_sizes, int n_in,
                              void* d_out, int out_size)
{
    const float* x  = (const float*)d_in[0];
    const float* y  = (const float*)d_in[1];
    const float* l1 = (const float*)d_in[2];
    const float* l2 = (const float*)d_in[3];
    const float* t1 = (const float*)d_in[4];
    const float* t2 = (const float*)d_in[5];
    const float* bl = (const float*)d_in[6];
    const float* bt = (const float*)d_in[7];

    prep_all<<<128, 128>>>(t2, l1, t1, l2);
    proj_mma<<<dim3(64, 4, 2), 128>>>(x, y, bl);
    flash_kernel<<<dim3(Ndim / 128, NHEAD, SPLIT), 128>>>();
    out_kernel<<<Bdim * Ndim / 16, 256>>>(bt, (float*)d_out);
}